// round 1
// baseline (speedup 1.0000x reference)
#include <cuda_runtime.h>
#include <math.h>

#define BB 4
#define TT 2048
#define CC 1024
#define HH 16
#define DH 64
#define BT (BB*TT)

// ---------------- scratch (static device globals; no runtime allocation) ----
__device__ float g_qkv[(size_t)BT * 3 * CC];     // [B*T][3C]   (96 MB)
__device__ float g_q[(size_t)BB*HH*TT*DH];       // [B,H,T,Dh]  (32 MB)
__device__ float g_k[(size_t)BB*HH*TT*DH];
__device__ float g_v[(size_t)BB*HH*TT*DH];
__device__ float g_att[(size_t)BT * CC];         // [B,T,C]     (32 MB)

// ---------------- SGEMM: C = A(MxK) @ B(KxN) + bias, fp32 -------------------
// 128x128 block tile, BK=8, 256 threads, 8x8 micro-tile per thread.
__global__ __launch_bounds__(256) void sgemm_bias(
    const float* __restrict__ A, const float* __restrict__ B,
    const float* __restrict__ bias, float* __restrict__ C,
    int M, int N, int K)
{
    constexpr int BM = 128, BN = 128, BK = 8;
    __shared__ float As[BK][BM];   // A tile stored transposed
    __shared__ float Bs[BK][BN];

    const int tid = threadIdx.x;
    const int tx  = tid & 15;
    const int ty  = tid >> 4;

    const float* Ab = A + (size_t)blockIdx.y * BM * K;
    const float* Bb = B + (size_t)blockIdx.x * BN;

    const int ar = tid >> 1;            // 0..127
    const int ac = (tid & 1) * 4;       // 0 or 4
    const int br = tid >> 5;            // 0..7
    const int bc = (tid & 31) * 4;      // 0..124

    float acc[8][8];
#pragma unroll
    for (int i = 0; i < 8; i++)
#pragma unroll
        for (int j = 0; j < 8; j++) acc[i][j] = 0.f;

    for (int k0 = 0; k0 < K; k0 += BK) {
        float4 av = *(const float4*)(Ab + (size_t)ar * K + k0 + ac);
        float4 bv = *(const float4*)(Bb + (size_t)(k0 + br) * N + bc);
        As[ac + 0][ar] = av.x;
        As[ac + 1][ar] = av.y;
        As[ac + 2][ar] = av.z;
        As[ac + 3][ar] = av.w;
        *(float4*)(&Bs[br][bc]) = bv;
        __syncthreads();

#pragma unroll
        for (int k = 0; k < BK; k++) {
            float a0[8], b0[8];
            *(float4*)(a0)     = *(const float4*)(&As[k][ty * 8]);
            *(float4*)(a0 + 4) = *(const float4*)(&As[k][ty * 8 + 4]);
            *(float4*)(b0)     = *(const float4*)(&Bs[k][tx * 8]);
            *(float4*)(b0 + 4) = *(const float4*)(&Bs[k][tx * 8 + 4]);
#pragma unroll
            for (int i = 0; i < 8; i++)
#pragma unroll
                for (int j = 0; j < 8; j++)
                    acc[i][j] += a0[i] * b0[j];
        }
        __syncthreads();
    }

    const int row0 = blockIdx.y * BM + ty * 8;
    const int col0 = blockIdx.x * BN + tx * 8;
    float bi[8];
    *(float4*)(bi)     = *(const float4*)(bias + col0);
    *(float4*)(bi + 4) = *(const float4*)(bias + col0 + 4);
#pragma unroll
    for (int i = 0; i < 8; i++) {
        float4 v0 = make_float4(acc[i][0] + bi[0], acc[i][1] + bi[1],
                                acc[i][2] + bi[2], acc[i][3] + bi[3]);
        float4 v1 = make_float4(acc[i][4] + bi[4], acc[i][5] + bi[5],
                                acc[i][6] + bi[6], acc[i][7] + bi[7]);
        *(float4*)(C + (size_t)(row0 + i) * N + col0)     = v0;
        *(float4*)(C + (size_t)(row0 + i) * N + col0 + 4) = v1;
    }
}

// ---------------- RoPE + split/transpose ------------------------------------
// One thread per (b,h,t,j) with j in [0,32): handles the (j, j+32) pair.
__global__ __launch_bounds__(256) void rope_split(
    const float* __restrict__ qkv,
    float* __restrict__ Qo, float* __restrict__ Ko, float* __restrict__ Vo)
{
    int idx = blockIdx.x * blockDim.x + threadIdx.x;
    if (idx >= BB * HH * TT * 32) return;
    int j = idx & 31;
    int t = (idx >> 5) & (TT - 1);
    int h = (idx >> 16) & (HH - 1);
    int b = idx >> 20;

    const float* base = qkv + ((size_t)(b * TT + t)) * (3 * CC) + h * DH;

    // inv_freq = 10000^(-j/32) computed as exp2f(-j * log2(10000)/32)
    float invf = exp2f(-(float)j * 0.41524101186f);
    float ang  = (float)t * invf;
    float sn, cs;
    sincosf(ang, &sn, &cs);

    size_t o = ((size_t)((b * HH + h) * TT + t)) * DH;

    float q1 = base[j],          q2 = base[j + 32];
    float k1 = base[CC + j],     k2 = base[CC + j + 32];
    float v1 = base[2 * CC + j], v2 = base[2 * CC + j + 32];

    Qo[o + j]      = q1 * cs - q2 * sn;
    Qo[o + j + 32] = q2 * cs + q1 * sn;
    Ko[o + j]      = k1 * cs - k2 * sn;
    Ko[o + j + 32] = k2 * cs + k1 * sn;
    Vo[o + j]      = v1;
    Vo[o + j + 32] = v2;
}

// ---------------- flash attention: 64 query rows / block, 64-key tiles ------
__global__ __launch_bounds__(256) void attn_fwd(
    const float* __restrict__ Q, const float* __restrict__ K,
    const float* __restrict__ V, float* __restrict__ O)
{
    constexpr int LD = 68;                  // padded row stride (floats)
    extern __shared__ float sm[];
    float* Qs = sm;                         // [64][LD]  Q (pre-scaled)
    float* Kt = sm + 64 * LD;               // [d][j]    K transposed
    float* Vs = Kt + 64 * LD;               // [j][d]
    float* Ps = Vs + 64 * LD;               // [i][j]

    const int tid = threadIdx.x;
    const int tx  = tid & 15;
    const int ty  = tid >> 4;
    const int bh  = blockIdx.y;             // b*16 + h
    const int q0  = blockIdx.x * 64;

    const float* Qg = Q + (size_t)bh * TT * DH + (size_t)q0 * DH;
    const float* Kg = K + (size_t)bh * TT * DH;
    const float* Vg = V + (size_t)bh * TT * DH;

    // load + scale Q tile (1/sqrt(64) = 0.125 folded in)
#pragma unroll
    for (int it = 0; it < 4; it++) {
        int idx = tid + it * 256;
        int r = idx >> 4, d4 = (idx & 15) << 2;
        float4 v = *(const float4*)(Qg + r * DH + d4);
        v.x *= 0.125f; v.y *= 0.125f; v.z *= 0.125f; v.w *= 0.125f;
        *(float4*)(Qs + r * LD + d4) = v;
    }

    float m[4], l[4], o[4][4];
#pragma unroll
    for (int r = 0; r < 4; r++) {
        m[r] = -1e30f; l[r] = 0.f;
#pragma unroll
        for (int c = 0; c < 4; c++) o[r][c] = 0.f;
    }

    for (int kb = 0; kb < TT; kb += 64) {
        __syncthreads();   // prior PV reads of Vs/Ps done
#pragma unroll
        for (int it = 0; it < 4; it++) {
            int idx = tid + it * 256;
            int r = idx >> 4, d4 = (idx & 15) << 2;
            float4 kv = *(const float4*)(Kg + (size_t)(kb + r) * DH + d4);
            Kt[(d4 + 0) * LD + r] = kv.x;
            Kt[(d4 + 1) * LD + r] = kv.y;
            Kt[(d4 + 2) * LD + r] = kv.z;
            Kt[(d4 + 3) * LD + r] = kv.w;
            *(float4*)(Vs + r * LD + d4) =
                *(const float4*)(Vg + (size_t)(kb + r) * DH + d4);
        }
        __syncthreads();

        // S = (Q*scale) @ K^T   (64x64, 4x4 per thread)
        float s[4][4];
#pragma unroll
        for (int r = 0; r < 4; r++)
#pragma unroll
            for (int c = 0; c < 4; c++) s[r][c] = 0.f;

#pragma unroll
        for (int d = 0; d < 64; d += 4) {
            float ar[4][4];
#pragma unroll
            for (int r = 0; r < 4; r++)
                *(float4*)(&ar[r][0]) = *(const float4*)(Qs + (ty * 4 + r) * LD + d);
#pragma unroll
            for (int dd = 0; dd < 4; dd++) {
                float4 bv = *(const float4*)(Kt + (d + dd) * LD + tx * 4);
#pragma unroll
                for (int r = 0; r < 4; r++) {
                    float q = ar[r][dd];
                    s[r][0] += q * bv.x;
                    s[r][1] += q * bv.y;
                    s[r][2] += q * bv.z;
                    s[r][3] += q * bv.w;
                }
            }
        }

        // online softmax (row groups span the 16 tx lanes of each half-warp)
#pragma unroll
        for (int r = 0; r < 4; r++) {
            float mx = fmaxf(fmaxf(s[r][0], s[r][1]), fmaxf(s[r][2], s[r][3]));
#pragma unroll
            for (int off = 8; off; off >>= 1)
                mx = fmaxf(mx, __shfl_xor_sync(0xffffffffu, mx, off));
            float mnew = fmaxf(m[r], mx);
            float corr = __expf(m[r] - mnew);
            float rs = 0.f;
#pragma unroll
            for (int c = 0; c < 4; c++) {
                float p = __expf(s[r][c] - mnew);
                Ps[(ty * 4 + r) * LD + tx * 4 + c] = p;
                rs += p;
            }
#pragma unroll
            for (int off = 8; off; off >>= 1)
                rs += __shfl_xor_sync(0xffffffffu, rs, off);
            l[r] = l[r] * corr + rs;
            m[r] = mnew;
            o[r][0] *= corr; o[r][1] *= corr; o[r][2] *= corr; o[r][3] *= corr;
        }
        __syncthreads();   // Ps visible

        // O += P @ V
#pragma unroll
        for (int j = 0; j < 64; j += 4) {
            float pr[4][4];
#pragma unroll
            for (int r = 0; r < 4; r++)
                *(float4*)(&pr[r][0]) = *(const float4*)(Ps + (ty * 4 + r) * LD + j);
#pragma unroll
            for (int jj = 0; jj < 4; jj++) {
                float4 bv = *(const float4*)(Vs + (j + jj) * LD + tx * 4);
#pragma unroll
                for (int r = 0; r < 4; r++) {
                    float p = pr[r][jj];
                    o[r][0] += p * bv.x;
                    o[r][1] += p * bv.y;
                    o[r][2] += p * bv.z;
                    o[r][3] += p * bv.w;
                }
            }
        }
    }

    // epilogue: write to [B,T,C] with C = h*64 + d
    const int b = bh >> 4, h = bh & 15;
#pragma unroll
    for (int r = 0; r < 4; r++) {
        float inv = 1.f / l[r];
        int t = q0 + ty * 4 + r;
        float4 ov = make_float4(o[r][0] * inv, o[r][1] * inv,
                                o[r][2] * inv, o[r][3] * inv);
        *(float4*)(O + ((size_t)(b * TT + t)) * CC + h * DH + tx * 4) = ov;
    }
}

// ---------------- launch ----------------------------------------------------
extern "C" void kernel_launch(void* const* d_in, const int* in_sizes, int n_in,
                              void* d_out, int out_size)
{
    const float* x    = (const float*)d_in[0];
    const float* Wqkv = (const float*)d_in[1];
    const float* bqkv = (const float*)d_in[2];
    const float* Wout = (const float*)d_in[3];
    const float* bout = (const float*)d_in[4];
    float* out = (float*)d_out;

    float *p_qkv, *p_q, *p_k, *p_v, *p_att;
    cudaGetSymbolAddress((void**)&p_qkv, g_qkv);
    cudaGetSymbolAddress((void**)&p_q,   g_q);
    cudaGetSymbolAddress((void**)&p_k,   g_k);
    cudaGetSymbolAddress((void**)&p_v,   g_v);
    cudaGetSymbolAddress((void**)&p_att, g_att);

    // 1) QKV projection: [8192,1024] @ [1024,3072] + bias
    sgemm_bias<<<dim3(3 * CC / 128, BT / 128), 256>>>(
        x, Wqkv, bqkv, p_qkv, BT, 3 * CC, CC);

    // 2) RoPE + split to [B,H,T,Dh]
    {
        int n = BB * HH * TT * 32;
        rope_split<<<n / 256, 256>>>(p_qkv, p_q, p_k, p_v);
    }

    // 3) attention
    {
        int smem = 4 * 64 * 68 * (int)sizeof(float);  // 69632 B
        cudaFuncSetAttribute(attn_fwd,
                             cudaFuncAttributeMaxDynamicSharedMemorySize, smem);
        attn_fwd<<<dim3(TT / 64, BB * HH), 256, smem>>>(p_q, p_k, p_v, p_att);
    }

    // 4) output projection: [8192,1024] @ [1024,1024] + bias
    sgemm_bias<<<dim3(CC / 128, BT / 128), 256>>>(
        p_att, Wout, bout, out, BT, CC, CC);
}

// round 3
// speedup vs baseline: 1.0973x; 1.0973x over previous
#include <cuda_runtime.h>
#include <cstdint>
#include <math.h>

#define BB 4
#define TT 2048
#define CC 1024
#define HH 16
#define DH 64
#define BT (BB*TT)

// ---------------- scratch (static device globals; no runtime allocation) ----
__device__ float g_qkv[(size_t)BT * 3 * CC];     // [B*T][3C]
__device__ float g_q[(size_t)BB*HH*TT*DH];       // [B,H,T,Dh]
__device__ float g_k[(size_t)BB*HH*TT*DH];
__device__ float g_v[(size_t)BB*HH*TT*DH];
__device__ float g_att[(size_t)BT * CC];         // [B,T,C]
__device__ float g_wqkvt[(size_t)3 * CC * CC];   // W_qkv^T  [3C][C]
__device__ float g_wot[(size_t)CC * CC];         // W_out^T  [C][C]

// ================= helpers ===================================================
__device__ __forceinline__ uint32_t f2tf32(float f) {
    uint32_t r;
    asm("cvt.rna.tf32.f32 %0, %1;" : "=r"(r) : "f"(f));
    return r;
}
__device__ __forceinline__ void mma_tf32(float* d, const uint32_t* a,
                                         const uint32_t* b) {
    asm volatile(
        "mma.sync.aligned.m16n8k8.row.col.f32.tf32.tf32.f32 "
        "{%0,%1,%2,%3}, {%4,%5,%6,%7}, {%8,%9}, {%0,%1,%2,%3};"
        : "+f"(d[0]), "+f"(d[1]), "+f"(d[2]), "+f"(d[3])
        : "r"(a[0]), "r"(a[1]), "r"(a[2]), "r"(a[3]), "r"(b[0]), "r"(b[1]));
}

// ================= transpose (W[K,N] -> Wt[N,K]) =============================
__global__ __launch_bounds__(256) void transpose_k(
    const float* __restrict__ W, float* __restrict__ Wt, int K, int N)
{
    __shared__ float t[32][33];
    int n0 = blockIdx.x * 32, k0 = blockIdx.y * 32;
    int lx = threadIdx.x & 31, ly = threadIdx.x >> 5;
#pragma unroll
    for (int i = 0; i < 32; i += 8)
        t[ly + i][lx] = W[(size_t)(k0 + ly + i) * N + n0 + lx];
    __syncthreads();
#pragma unroll
    for (int i = 0; i < 32; i += 8)
        Wt[(size_t)(n0 + ly + i) * K + k0 + lx] = t[lx][ly + i];
}

// ================= 3xTF32 mma.sync GEMM ======================================
// C[M,N] = A[M,K] @ Bt[N,K]^T + bias
// CTA tile 128x128, BK=16, 8 warps (warp tile 32m x 64n), double-buffered.
// smem per stage (floats): A[128][36] (hi k0..15, lo k16..31, pad 4), B same.
#define GLD   36                 // padded row stride (floats)
#define GSTG  (128 * GLD)        // floats per matrix per stage (4608)

__global__ __launch_bounds__(256, 1) void gemm_tf32x3(
    const float* __restrict__ A, const float* __restrict__ Bt,
    const float* __restrict__ bias, float* __restrict__ C,
    int M, int N, int K)
{
    extern __shared__ float smf[];
    const int tid  = threadIdx.x;
    const int lane = tid & 31, gid = lane >> 2, t4 = lane & 3;
    const int wid  = tid >> 5;
    const int wm   = wid & 3;          // 0..3 -> m offset wm*32
    const int wn   = wid >> 2;         // 0..1 -> n offset wn*64
    const int tile_n = blockIdx.x * 128, tile_m = blockIdx.y * 128;

    const float* Ab = A  + (size_t)tile_m * K;
    const float* Bb = Bt + (size_t)tile_n * K;

    // staging indices: 512 float4 per matrix; this thread handles f = tid, tid+256
    const int r0s = tid >> 2,        kc0 = (tid & 3) * 4;
    const int r1s = (tid + 256) >> 2, kc1 = ((tid + 256) & 3) * 4;

    float acc[2][8][4];
#pragma unroll
    for (int ma = 0; ma < 2; ma++)
#pragma unroll
        for (int na = 0; na < 8; na++)
#pragma unroll
            for (int c = 0; c < 4; c++) acc[ma][na][c] = 0.f;

    const int kiters = K / 16;
    float4 ra0, ra1, rb0, rb1;

    // prologue: load iter 0
    ra0 = *(const float4*)(Ab + (size_t)r0s * K + kc0);
    ra1 = *(const float4*)(Ab + (size_t)r1s * K + kc1);
    rb0 = *(const float4*)(Bb + (size_t)r0s * K + kc0);
    rb1 = *(const float4*)(Bb + (size_t)r1s * K + kc1);

    for (int it = 0; it < kiters; it++) {
        const int st = it & 1;
        float* As = smf + st * (2 * GSTG);
        float* Bs = As + GSTG;

        // ---- stage regs -> smem (convert to hi/lo tf32) ----
        {
            float4 v; uint4 h, l;
#define CVT4(vv, hh, ll)                                                     \
            hh.x = f2tf32(vv.x); ll.x = f2tf32(vv.x - __uint_as_float(hh.x)); \
            hh.y = f2tf32(vv.y); ll.y = f2tf32(vv.y - __uint_as_float(hh.y)); \
            hh.z = f2tf32(vv.z); ll.z = f2tf32(vv.z - __uint_as_float(hh.z)); \
            hh.w = f2tf32(vv.w); ll.w = f2tf32(vv.w - __uint_as_float(hh.w));
            v = ra0; CVT4(v, h, l);
            *(uint4*)(As + r0s * GLD + kc0)      = h;
            *(uint4*)(As + r0s * GLD + 16 + kc0) = l;
            v = ra1; CVT4(v, h, l);
            *(uint4*)(As + r1s * GLD + kc1)      = h;
            *(uint4*)(As + r1s * GLD + 16 + kc1) = l;
            v = rb0; CVT4(v, h, l);
            *(uint4*)(Bs + r0s * GLD + kc0)      = h;
            *(uint4*)(Bs + r0s * GLD + 16 + kc0) = l;
            v = rb1; CVT4(v, h, l);
            *(uint4*)(Bs + r1s * GLD + kc1)      = h;
            *(uint4*)(Bs + r1s * GLD + 16 + kc1) = l;
#undef CVT4
        }
        __syncthreads();

        // ---- prefetch next iter ----
        if (it + 1 < kiters) {
            const float* Ag = Ab + (it + 1) * 16;
            const float* Bg = Bb + (it + 1) * 16;
            ra0 = *(const float4*)(Ag + (size_t)r0s * K + kc0);
            ra1 = *(const float4*)(Ag + (size_t)r1s * K + kc1);
            rb0 = *(const float4*)(Bg + (size_t)r0s * K + kc0);
            rb1 = *(const float4*)(Bg + (size_t)r1s * K + kc1);
        }

        // ---- compute: 2 k-steps of 8 ----
#pragma unroll
        for (int ks = 0; ks < 16; ks += 8) {
            uint32_t ah[2][4], al[2][4], bh[8][2], bl[8][2];
#pragma unroll
            for (int ma = 0; ma < 2; ma++) {
                const float* p = As + (wm * 32 + ma * 16 + gid) * GLD + ks + t4;
                ah[ma][0] = __float_as_uint(p[0]);
                ah[ma][1] = __float_as_uint(p[8 * GLD]);
                ah[ma][2] = __float_as_uint(p[4]);
                ah[ma][3] = __float_as_uint(p[8 * GLD + 4]);
                al[ma][0] = __float_as_uint(p[16]);
                al[ma][1] = __float_as_uint(p[8 * GLD + 16]);
                al[ma][2] = __float_as_uint(p[20]);
                al[ma][3] = __float_as_uint(p[8 * GLD + 20]);
            }
#pragma unroll
            for (int na = 0; na < 8; na++) {
                const float* p = Bs + (wn * 64 + na * 8 + gid) * GLD + ks + t4;
                bh[na][0] = __float_as_uint(p[0]);
                bh[na][1] = __float_as_uint(p[4]);
                bl[na][0] = __float_as_uint(p[16]);
                bl[na][1] = __float_as_uint(p[20]);
            }
#pragma unroll
            for (int ma = 0; ma < 2; ma++)
#pragma unroll
                for (int na = 0; na < 8; na++) {
                    mma_tf32(acc[ma][na], ah[ma], bl[na]);
                    mma_tf32(acc[ma][na], al[ma], bh[na]);
                    mma_tf32(acc[ma][na], ah[ma], bh[na]);
                }
        }
        __syncthreads();
    }

    // ---- epilogue: bias + store ----
#pragma unroll
    for (int ma = 0; ma < 2; ma++) {
        const int r0 = tile_m + wm * 32 + ma * 16 + gid;
#pragma unroll
        for (int na = 0; na < 8; na++) {
            const int c0 = tile_n + wn * 64 + na * 8 + t4 * 2;
            float2 bv = *(const float2*)(bias + c0);
            float2 o0 = make_float2(acc[ma][na][0] + bv.x,
                                    acc[ma][na][1] + bv.y);
            float2 o1 = make_float2(acc[ma][na][2] + bv.x,
                                    acc[ma][na][3] + bv.y);
            *(float2*)(C + (size_t)r0 * N + c0)       = o0;
            *(float2*)(C + (size_t)(r0 + 8) * N + c0) = o1;
        }
    }
}

// ---------------- RoPE + split/transpose ------------------------------------
__global__ __launch_bounds__(256) void rope_split(
    const float* __restrict__ qkv,
    float* __restrict__ Qo, float* __restrict__ Ko, float* __restrict__ Vo)
{
    int idx = blockIdx.x * blockDim.x + threadIdx.x;
    if (idx >= BB * HH * TT * 32) return;
    int j = idx & 31;
    int t = (idx >> 5) & (TT - 1);
    int h = (idx >> 16) & (HH - 1);
    int b = idx >> 20;

    const float* base = qkv + ((size_t)(b * TT + t)) * (3 * CC) + h * DH;

    float invf = exp2f(-(float)j * 0.41524101186f);
    float ang  = (float)t * invf;
    float sn, cs;
    sincosf(ang, &sn, &cs);

    size_t o = ((size_t)((b * HH + h) * TT + t)) * DH;

    float q1 = base[j],          q2 = base[j + 32];
    float k1 = base[CC + j],     k2 = base[CC + j + 32];
    float v1 = base[2 * CC + j], v2 = base[2 * CC + j + 32];

    Qo[o + j]      = q1 * cs - q2 * sn;
    Qo[o + j + 32] = q2 * cs + q1 * sn;
    Ko[o + j]      = k1 * cs - k2 * sn;
    Ko[o + j + 32] = k2 * cs + k1 * sn;
    Vo[o + j]      = v1;
    Vo[o + j + 32] = v2;
}

// ---------------- flash attention: 64 query rows / block, 64-key tiles ------
__global__ __launch_bounds__(256) void attn_fwd(
    const float* __restrict__ Q, const float* __restrict__ K,
    const float* __restrict__ V, float* __restrict__ O)
{
    constexpr int LD = 68;
    extern __shared__ float smfa[];
    float* Qs = smfa;
    float* Kt = smfa + 64 * LD;
    float* Vs = Kt + 64 * LD;
    float* Ps = Vs + 64 * LD;

    const int tid = threadIdx.x;
    const int tx  = tid & 15;
    const int ty  = tid >> 4;
    const int bh  = blockIdx.y;
    const int q0  = blockIdx.x * 64;

    const float* Qg = Q + (size_t)bh * TT * DH + (size_t)q0 * DH;
    const float* Kg = K + (size_t)bh * TT * DH;
    const float* Vg = V + (size_t)bh * TT * DH;

#pragma unroll
    for (int it = 0; it < 4; it++) {
        int idx = tid + it * 256;
        int r = idx >> 4, d4 = (idx & 15) << 2;
        float4 v = *(const float4*)(Qg + r * DH + d4);
        v.x *= 0.125f; v.y *= 0.125f; v.z *= 0.125f; v.w *= 0.125f;
        *(float4*)(Qs + r * LD + d4) = v;
    }

    float m[4], l[4], o[4][4];
#pragma unroll
    for (int r = 0; r < 4; r++) {
        m[r] = -1e30f; l[r] = 0.f;
#pragma unroll
        for (int c = 0; c < 4; c++) o[r][c] = 0.f;
    }

    for (int kb = 0; kb < TT; kb += 64) {
        __syncthreads();
#pragma unroll
        for (int it = 0; it < 4; it++) {
            int idx = tid + it * 256;
            int r = idx >> 4, d4 = (idx & 15) << 2;
            float4 kv = *(const float4*)(Kg + (size_t)(kb + r) * DH + d4);
            Kt[(d4 + 0) * LD + r] = kv.x;
            Kt[(d4 + 1) * LD + r] = kv.y;
            Kt[(d4 + 2) * LD + r] = kv.z;
            Kt[(d4 + 3) * LD + r] = kv.w;
            *(float4*)(Vs + r * LD + d4) =
                *(const float4*)(Vg + (size_t)(kb + r) * DH + d4);
        }
        __syncthreads();

        float s[4][4];
#pragma unroll
        for (int r = 0; r < 4; r++)
#pragma unroll
            for (int c = 0; c < 4; c++) s[r][c] = 0.f;

#pragma unroll
        for (int d = 0; d < 64; d += 4) {
            float ar[4][4];
#pragma unroll
            for (int r = 0; r < 4; r++)
                *(float4*)(&ar[r][0]) = *(const float4*)(Qs + (ty * 4 + r) * LD + d);
#pragma unroll
            for (int dd = 0; dd < 4; dd++) {
                float4 bv = *(const float4*)(Kt + (d + dd) * LD + tx * 4);
#pragma unroll
                for (int r = 0; r < 4; r++) {
                    float q = ar[r][dd];
                    s[r][0] += q * bv.x;
                    s[r][1] += q * bv.y;
                    s[r][2] += q * bv.z;
                    s[r][3] += q * bv.w;
                }
            }
        }

#pragma unroll
        for (int r = 0; r < 4; r++) {
            float mx = fmaxf(fmaxf(s[r][0], s[r][1]), fmaxf(s[r][2], s[r][3]));
#pragma unroll
            for (int off = 8; off; off >>= 1)
                mx = fmaxf(mx, __shfl_xor_sync(0xffffffffu, mx, off));
            float mnew = fmaxf(m[r], mx);
            float corr = __expf(m[r] - mnew);
            float rs = 0.f;
#pragma unroll
            for (int c = 0; c < 4; c++) {
                float p = __expf(s[r][c] - mnew);
                Ps[(ty * 4 + r) * LD + tx * 4 + c] = p;
                rs += p;
            }
#pragma unroll
            for (int off = 8; off; off >>= 1)
                rs += __shfl_xor_sync(0xffffffffu, rs, off);
            l[r] = l[r] * corr + rs;
            m[r] = mnew;
            o[r][0] *= corr; o[r][1] *= corr; o[r][2] *= corr; o[r][3] *= corr;
        }
        __syncthreads();

#pragma unroll
        for (int j = 0; j < 64; j += 4) {
            float pr[4][4];
#pragma unroll
            for (int r = 0; r < 4; r++)
                *(float4*)(&pr[r][0]) = *(const float4*)(Ps + (ty * 4 + r) * LD + j);
#pragma unroll
            for (int jj = 0; jj < 4; jj++) {
                float4 bv = *(const float4*)(Vs + (j + jj) * LD + tx * 4);
#pragma unroll
                for (int r = 0; r < 4; r++) {
                    float p = pr[r][jj];
                    o[r][0] += p * bv.x;
                    o[r][1] += p * bv.y;
                    o[r][2] += p * bv.z;
                    o[r][3] += p * bv.w;
                }
            }
        }
    }

    const int b = bh >> 4, h = bh & 15;
#pragma unroll
    for (int r = 0; r < 4; r++) {
        float inv = 1.f / l[r];
        int t = q0 + ty * 4 + r;
        float4 ov = make_float4(o[r][0] * inv, o[r][1] * inv,
                                o[r][2] * inv, o[r][3] * inv);
        *(float4*)(O + ((size_t)(b * TT + t)) * CC + h * DH + tx * 4) = ov;
    }
}

// ---------------- launch ----------------------------------------------------
extern "C" void kernel_launch(void* const* d_in, const int* in_sizes, int n_in,
                              void* d_out, int out_size)
{
    const float* x    = (const float*)d_in[0];
    const float* Wqkv = (const float*)d_in[1];
    const float* bqkv = (const float*)d_in[2];
    const float* Wout = (const float*)d_in[3];
    const float* bout = (const float*)d_in[4];
    float* out = (float*)d_out;

    float *p_qkv, *p_q, *p_k, *p_v, *p_att, *p_wqkvt, *p_wot;
    cudaGetSymbolAddress((void**)&p_qkv,   g_qkv);
    cudaGetSymbolAddress((void**)&p_q,     g_q);
    cudaGetSymbolAddress((void**)&p_k,     g_k);
    cudaGetSymbolAddress((void**)&p_v,     g_v);
    cudaGetSymbolAddress((void**)&p_att,   g_att);
    cudaGetSymbolAddress((void**)&p_wqkvt, g_wqkvt);
    cudaGetSymbolAddress((void**)&p_wot,   g_wot);

    const int gemm_smem = 2 * 2 * GSTG * (int)sizeof(float);  // 73728 B
    cudaFuncSetAttribute(gemm_tf32x3,
                         cudaFuncAttributeMaxDynamicSharedMemorySize, gemm_smem);
    cudaFuncSetAttribute(attn_fwd,
                         cudaFuncAttributeMaxDynamicSharedMemorySize,
                         4 * 64 * 68 * (int)sizeof(float));

    // 0) transpose weights to K-major
    transpose_k<<<dim3(3 * CC / 32, CC / 32), 256>>>(Wqkv, p_wqkvt, CC, 3 * CC);
    transpose_k<<<dim3(CC / 32, CC / 32), 256>>>(Wout, p_wot, CC, CC);

    // 1) QKV projection: [8192,1024] @ [1024,3072] + bias  (3xTF32 mma.sync)
    gemm_tf32x3<<<dim3(3 * CC / 128, BT / 128), 256, gemm_smem>>>(
        x, p_wqkvt, bqkv, p_qkv, BT, 3 * CC, CC);

    // 2) RoPE + split to [B,H,T,Dh]
    {
        int n = BB * HH * TT * 32;
        rope_split<<<n / 256, 256>>>(p_qkv, p_q, p_k, p_v);
    }

    // 3) attention (fp32 SIMT, unchanged this round)
    {
        int smem = 4 * 64 * 68 * (int)sizeof(float);
        attn_fwd<<<dim3(TT / 64, BB * HH), 256, smem>>>(p_q, p_k, p_v, p_att);
    }

    // 4) output projection: [8192,1024] @ [1024,1024] + bias  (3xTF32 mma.sync)
    gemm_tf32x3<<<dim3(CC / 128, BT / 128), 256, gemm_smem>>>(
        p_att, p_wot, bout, out, BT, CC, CC);
}

// round 4
// speedup vs baseline: 1.9379x; 1.7661x over previous
#include <cuda_runtime.h>
#include <cuda_bf16.h>
#include <cstdint>
#include <math.h>

#define BB 4
#define TT 2048
#define CC 1024
#define HH 16
#define DH 64
#define BT (BB*TT)

// ---------------- scratch (static device globals; no runtime allocation) ----
__device__ float g_qkv[(size_t)BT * 3 * CC];     // [B*T][3C]
__device__ float g_q[(size_t)BB*HH*TT*DH];       // [B,H,T,Dh]
__device__ float g_k[(size_t)BB*HH*TT*DH];
__device__ float g_v[(size_t)BB*HH*TT*DH];
__device__ float g_att[(size_t)BT * CC];         // [B,T,C]
__device__ float g_wqkvt[(size_t)3 * CC * CC];   // W_qkv^T  [3C][C]
__device__ float g_wot[(size_t)CC * CC];         // W_out^T  [C][C]

// ================= helpers ===================================================
__device__ __forceinline__ uint32_t smem_u32(const void* p) {
    uint32_t a;
    asm("{ .reg .u64 t; cvta.to.shared.u64 t, %1; cvt.u32.u64 %0, t; }"
        : "=r"(a) : "l"(p));
    return a;
}
__device__ __forceinline__ uint32_t bpack(float a, float b) {
    __nv_bfloat162 t;
    t.x = __float2bfloat16(a);
    t.y = __float2bfloat16(b);
    return *reinterpret_cast<uint32_t*>(&t);
}
__device__ __forceinline__ uint32_t bpack_lo(float a, float b, uint32_t hp) {
    __nv_bfloat162 h = *reinterpret_cast<__nv_bfloat162*>(&hp);
    return bpack(a - __bfloat162float(h.x), b - __bfloat162float(h.y));
}
__device__ __forceinline__ void cvt4(float4 v, uint2& h, uint2& l) {
    h.x = bpack(v.x, v.y);
    h.y = bpack(v.z, v.w);
    l.x = bpack_lo(v.x, v.y, h.x);
    l.y = bpack_lo(v.z, v.w, h.y);
}
__device__ __forceinline__ void mma_bf16(float* d, const uint32_t* a,
                                         const uint32_t* b) {
    asm volatile(
        "mma.sync.aligned.m16n8k16.row.col.f32.bf16.bf16.f32 "
        "{%0,%1,%2,%3}, {%4,%5,%6,%7}, {%8,%9}, {%0,%1,%2,%3};"
        : "+f"(d[0]), "+f"(d[1]), "+f"(d[2]), "+f"(d[3])
        : "r"(a[0]), "r"(a[1]), "r"(a[2]), "r"(a[3]), "r"(b[0]), "r"(b[1]));
}
#define LDSM_X2_T(r0, r1, addr)                                               \
    asm volatile("ldmatrix.sync.aligned.m8n8.x2.trans.shared.b16 {%0,%1}, [%2];" \
                 : "=r"(r0), "=r"(r1) : "r"(addr))
#define L32(p) (*(const uint32_t*)(p))

// fast exp on FMA pipe (x <= 0); rel err ~2.4e-6, no MUFU
__device__ __forceinline__ float expfast(float x) {
    float y = fmaxf(x * 1.4426950408889634f, -126.0f);
    int   ni = __float2int_rn(y);
    float f  = y - (float)ni;
    float p = 0.0013333558146428443f;
    p = fmaf(p, f, 0.009618129107628477f);
    p = fmaf(p, f, 0.05550410866482158f);
    p = fmaf(p, f, 0.2402265069591007f);
    p = fmaf(p, f, 0.6931471805599453f);
    p = fmaf(p, f, 1.0f);
    return p * __int_as_float((ni + 127) << 23);
}

// ================= transpose (W[K,N] -> Wt[N,K]) =============================
__global__ __launch_bounds__(256) void transpose_k(
    const float* __restrict__ W, float* __restrict__ Wt, int K, int N)
{
    __shared__ float t[32][33];
    int n0 = blockIdx.x * 32, k0 = blockIdx.y * 32;
    int lx = threadIdx.x & 31, ly = threadIdx.x >> 5;
#pragma unroll
    for (int i = 0; i < 32; i += 8)
        t[ly + i][lx] = W[(size_t)(k0 + ly + i) * N + n0 + lx];
    __syncthreads();
#pragma unroll
    for (int i = 0; i < 32; i += 8)
        Wt[(size_t)(n0 + ly + i) * K + k0 + lx] = t[lx][ly + i];
}

// ================= 3xBF16 mma.sync GEMM ======================================
// C[M,N] = A[M,K] @ Bt[N,K]^T + bias
// CTA tile 128x128, BK=16, 8 warps (warp tile 32m x 64n), double-buffered.
// stage layout per matrix: [128 rows][40 halves]: hi k0..15 @0, lo k0..15 @16.
#define GLD  40
#define GSTG (128 * GLD)       // halves per matrix per stage

__global__ __launch_bounds__(256, 1) void gemm_bf16x3(
    const float* __restrict__ A, const float* __restrict__ Bt,
    const float* __restrict__ bias, float* __restrict__ C,
    int M, int N, int K)
{
    extern __shared__ __nv_bfloat16 smh[];
    const int tid  = threadIdx.x;
    const int lane = tid & 31, gid = lane >> 2, t4 = lane & 3;
    const int wid  = tid >> 5;
    const int wm   = wid & 3;
    const int wn   = wid >> 2;
    const int tile_n = blockIdx.x * 128, tile_m = blockIdx.y * 128;

    const float* Ab = A  + (size_t)tile_m * K;
    const float* Bb = Bt + (size_t)tile_n * K;

    const int r0s = tid >> 2,         kc0 = (tid & 3) * 4;
    const int r1s = (tid + 256) >> 2, kc1 = ((tid + 256) & 3) * 4;

    float acc[2][8][4];
#pragma unroll
    for (int ma = 0; ma < 2; ma++)
#pragma unroll
        for (int na = 0; na < 8; na++)
#pragma unroll
            for (int c = 0; c < 4; c++) acc[ma][na][c] = 0.f;

    const int kiters = K / 16;
    float4 ra0, ra1, rb0, rb1;
    ra0 = *(const float4*)(Ab + (size_t)r0s * K + kc0);
    ra1 = *(const float4*)(Ab + (size_t)r1s * K + kc1);
    rb0 = *(const float4*)(Bb + (size_t)r0s * K + kc0);
    rb1 = *(const float4*)(Bb + (size_t)r1s * K + kc1);

    for (int it = 0; it < kiters; it++) {
        const int st = it & 1;
        __nv_bfloat16* As = smh + st * (2 * GSTG);
        __nv_bfloat16* Bs = As + GSTG;

        {
            uint2 h, l;
            cvt4(ra0, h, l);
            *(uint2*)(As + r0s * GLD + kc0)      = h;
            *(uint2*)(As + r0s * GLD + 16 + kc0) = l;
            cvt4(ra1, h, l);
            *(uint2*)(As + r1s * GLD + kc1)      = h;
            *(uint2*)(As + r1s * GLD + 16 + kc1) = l;
            cvt4(rb0, h, l);
            *(uint2*)(Bs + r0s * GLD + kc0)      = h;
            *(uint2*)(Bs + r0s * GLD + 16 + kc0) = l;
            cvt4(rb1, h, l);
            *(uint2*)(Bs + r1s * GLD + kc1)      = h;
            *(uint2*)(Bs + r1s * GLD + 16 + kc1) = l;
        }
        __syncthreads();

        if (it + 1 < kiters) {
            const float* Ag = Ab + (it + 1) * 16;
            const float* Bg = Bb + (it + 1) * 16;
            ra0 = *(const float4*)(Ag + (size_t)r0s * K + kc0);
            ra1 = *(const float4*)(Ag + (size_t)r1s * K + kc1);
            rb0 = *(const float4*)(Bg + (size_t)r0s * K + kc0);
            rb1 = *(const float4*)(Bg + (size_t)r1s * K + kc1);
        }

        uint32_t ah[2][4], al[2][4], bh[8][2], bl[8][2];
#pragma unroll
        for (int ma = 0; ma < 2; ma++) {
            const __nv_bfloat16* p = As + (wm * 32 + ma * 16 + gid) * GLD + 2 * t4;
            ah[ma][0] = L32(p);
            ah[ma][1] = L32(p + 8 * GLD);
            ah[ma][2] = L32(p + 8);
            ah[ma][3] = L32(p + 8 * GLD + 8);
            al[ma][0] = L32(p + 16);
            al[ma][1] = L32(p + 8 * GLD + 16);
            al[ma][2] = L32(p + 24);
            al[ma][3] = L32(p + 8 * GLD + 24);
        }
#pragma unroll
        for (int na = 0; na < 8; na++) {
            const __nv_bfloat16* p = Bs + (wn * 64 + na * 8 + gid) * GLD + 2 * t4;
            bh[na][0] = L32(p);
            bh[na][1] = L32(p + 8);
            bl[na][0] = L32(p + 16);
            bl[na][1] = L32(p + 24);
        }
#pragma unroll
        for (int ma = 0; ma < 2; ma++)
#pragma unroll
            for (int na = 0; na < 8; na++) {
                mma_bf16(acc[ma][na], ah[ma], bl[na]);
                mma_bf16(acc[ma][na], al[ma], bh[na]);
                mma_bf16(acc[ma][na], ah[ma], bh[na]);
            }
        __syncthreads();
    }

#pragma unroll
    for (int ma = 0; ma < 2; ma++) {
        const int r0 = tile_m + wm * 32 + ma * 16 + gid;
#pragma unroll
        for (int na = 0; na < 8; na++) {
            const int c0 = tile_n + wn * 64 + na * 8 + t4 * 2;
            float2 bv = *(const float2*)(bias + c0);
            *(float2*)(C + (size_t)r0 * N + c0) =
                make_float2(acc[ma][na][0] + bv.x, acc[ma][na][1] + bv.y);
            *(float2*)(C + (size_t)(r0 + 8) * N + c0) =
                make_float2(acc[ma][na][2] + bv.x, acc[ma][na][3] + bv.y);
        }
    }
}

// ---------------- RoPE + split/transpose ------------------------------------
__global__ __launch_bounds__(256) void rope_split(
    const float* __restrict__ qkv,
    float* __restrict__ Qo, float* __restrict__ Ko, float* __restrict__ Vo)
{
    int idx = blockIdx.x * blockDim.x + threadIdx.x;
    if (idx >= BB * HH * TT * 32) return;
    int j = idx & 31;
    int t = (idx >> 5) & (TT - 1);
    int h = (idx >> 16) & (HH - 1);
    int b = idx >> 20;

    const float* base = qkv + ((size_t)(b * TT + t)) * (3 * CC) + h * DH;

    float invf = exp2f(-(float)j * 0.41524101186f);
    float ang  = (float)t * invf;
    float sn, cs;
    sincosf(ang, &sn, &cs);

    size_t o = ((size_t)((b * HH + h) * TT + t)) * DH;

    float q1 = base[j],          q2 = base[j + 32];
    float k1 = base[CC + j],     k2 = base[CC + j + 32];
    float v1 = base[2 * CC + j], v2 = base[2 * CC + j + 32];

    Qo[o + j]      = q1 * cs - q2 * sn;
    Qo[o + j + 32] = q2 * cs + q1 * sn;
    Ko[o + j]      = k1 * cs - k2 * sn;
    Ko[o + j + 32] = k2 * cs + k1 * sn;
    Vo[o + j]      = v1;
    Vo[o + j + 32] = v2;
}

// ================= FA2 attention: bf16x3 mma + poly exp ======================
// CTA: 64 q rows (blockIdx.x), one (b,h) (blockIdx.y). 4 warps x 16 q rows.
// K/V tiles 64 keys staged as bf16 hi/lo: [64 rows][136 halves] (hi 0-63, lo 64-127).
#define ALD 136

__global__ __launch_bounds__(128) void attn_mma(
    const float* __restrict__ Q, const float* __restrict__ K,
    const float* __restrict__ V, float* __restrict__ O)
{
    __shared__ __nv_bfloat16 Ks[64 * ALD];
    __shared__ __nv_bfloat16 Vs[64 * ALD];

    const int tid = threadIdx.x;
    const int lane = tid & 31, gid = lane >> 2, t4 = lane & 3;
    const int w = tid >> 5;
    const int bh = blockIdx.y;
    const int q0 = blockIdx.x * 64;
    const int b = bh >> 4, h = bh & 15;

    const float* Qg = Q + (size_t)bh * TT * DH + (size_t)q0 * DH;
    const float* Kg = K + (size_t)bh * TT * DH;
    const float* Vg = V + (size_t)bh * TT * DH;

    const uint32_t vsb = smem_u32(Vs);

    // ---- stage Q (pre-scaled) through Ks, load frags to regs ----
#pragma unroll
    for (int it = 0; it < 8; it++) {
        int f = tid + it * 128;
        int row = f >> 4, c4 = (f & 15) * 4;
        float4 v = *(const float4*)(Qg + row * DH + c4);
        v.x *= 0.125f; v.y *= 0.125f; v.z *= 0.125f; v.w *= 0.125f;
        uint2 hh, ll;
        cvt4(v, hh, ll);
        *(uint2*)(Ks + row * ALD + c4)      = hh;
        *(uint2*)(Ks + row * ALD + 64 + c4) = ll;
    }
    __syncthreads();

    uint32_t qh[4][4], ql[4][4];
#pragma unroll
    for (int ks = 0; ks < 4; ks++) {
        const __nv_bfloat16* p = Ks + (w * 16 + gid) * ALD + ks * 16 + 2 * t4;
        qh[ks][0] = L32(p);
        qh[ks][1] = L32(p + 8 * ALD);
        qh[ks][2] = L32(p + 8);
        qh[ks][3] = L32(p + 8 * ALD + 8);
        ql[ks][0] = L32(p + 64);
        ql[ks][1] = L32(p + 8 * ALD + 64);
        ql[ks][2] = L32(p + 72);
        ql[ks][3] = L32(p + 8 * ALD + 72);
    }
    __syncthreads();

    float m0 = -1e30f, m1 = -1e30f, l0 = 0.f, l1 = 0.f;
    float o[8][4];
#pragma unroll
    for (int nd = 0; nd < 8; nd++)
#pragma unroll
        for (int c = 0; c < 4; c++) o[nd][c] = 0.f;

    for (int kb = 0; kb < TT; kb += 64) {
        // ---- stage K, V ----
#pragma unroll
        for (int it = 0; it < 8; it++) {
            int f = tid + it * 128;
            int row = f >> 4, c4 = (f & 15) * 4;
            uint2 hh, ll;
            float4 kv = *(const float4*)(Kg + (size_t)(kb + row) * DH + c4);
            cvt4(kv, hh, ll);
            *(uint2*)(Ks + row * ALD + c4)      = hh;
            *(uint2*)(Ks + row * ALD + 64 + c4) = ll;
            float4 vv = *(const float4*)(Vg + (size_t)(kb + row) * DH + c4);
            cvt4(vv, hh, ll);
            *(uint2*)(Vs + row * ALD + c4)      = hh;
            *(uint2*)(Vs + row * ALD + 64 + c4) = ll;
        }
        __syncthreads();

        // ---- S = Q @ K^T ----
        float s[8][4];
#pragma unroll
        for (int n = 0; n < 8; n++)
#pragma unroll
            for (int c = 0; c < 4; c++) s[n][c] = 0.f;

#pragma unroll
        for (int ks = 0; ks < 4; ks++) {
#pragma unroll
            for (int n = 0; n < 8; n++) {
                const __nv_bfloat16* p = Ks + (n * 8 + gid) * ALD + ks * 16 + 2 * t4;
                uint32_t kbh[2], kbl[2];
                kbh[0] = L32(p);
                kbh[1] = L32(p + 8);
                kbl[0] = L32(p + 64);
                kbl[1] = L32(p + 72);
                mma_bf16(s[n], qh[ks], kbl);
                mma_bf16(s[n], ql[ks], kbh);
                mma_bf16(s[n], qh[ks], kbh);
            }
        }

        // ---- online softmax (rows gid, gid+8) ----
        float mx0 = -1e30f, mx1 = -1e30f;
#pragma unroll
        for (int n = 0; n < 8; n++) {
            mx0 = fmaxf(mx0, fmaxf(s[n][0], s[n][1]));
            mx1 = fmaxf(mx1, fmaxf(s[n][2], s[n][3]));
        }
        mx0 = fmaxf(mx0, __shfl_xor_sync(0xffffffffu, mx0, 1));
        mx0 = fmaxf(mx0, __shfl_xor_sync(0xffffffffu, mx0, 2));
        mx1 = fmaxf(mx1, __shfl_xor_sync(0xffffffffu, mx1, 1));
        mx1 = fmaxf(mx1, __shfl_xor_sync(0xffffffffu, mx1, 2));

        float m0n = fmaxf(m0, mx0), m1n = fmaxf(m1, mx1);
        float c0 = expfast(m0 - m0n), c1 = expfast(m1 - m1n);
        float s0 = 0.f, s1 = 0.f;
#pragma unroll
        for (int n = 0; n < 8; n++) {
            s[n][0] = expfast(s[n][0] - m0n); s0 += s[n][0];
            s[n][1] = expfast(s[n][1] - m0n); s0 += s[n][1];
            s[n][2] = expfast(s[n][2] - m1n); s1 += s[n][2];
            s[n][3] = expfast(s[n][3] - m1n); s1 += s[n][3];
        }
        s0 += __shfl_xor_sync(0xffffffffu, s0, 1);
        s0 += __shfl_xor_sync(0xffffffffu, s0, 2);
        s1 += __shfl_xor_sync(0xffffffffu, s1, 1);
        s1 += __shfl_xor_sync(0xffffffffu, s1, 2);
        l0 = l0 * c0 + s0;
        l1 = l1 * c1 + s1;
        m0 = m0n; m1 = m1n;
#pragma unroll
        for (int nd = 0; nd < 8; nd++) {
            o[nd][0] *= c0; o[nd][1] *= c0;
            o[nd][2] *= c1; o[nd][3] *= c1;
        }

        // ---- O += P @ V ----
#pragma unroll
        for (int j = 0; j < 4; j++) {
            uint32_t pah[4], pal[4];
            pah[0] = bpack(s[2 * j][0],     s[2 * j][1]);
            pah[1] = bpack(s[2 * j][2],     s[2 * j][3]);
            pah[2] = bpack(s[2 * j + 1][0], s[2 * j + 1][1]);
            pah[3] = bpack(s[2 * j + 1][2], s[2 * j + 1][3]);
            pal[0] = bpack_lo(s[2 * j][0],     s[2 * j][1],     pah[0]);
            pal[1] = bpack_lo(s[2 * j][2],     s[2 * j][3],     pah[1]);
            pal[2] = bpack_lo(s[2 * j + 1][0], s[2 * j + 1][1], pah[2]);
            pal[3] = bpack_lo(s[2 * j + 1][2], s[2 * j + 1][3], pah[3]);

            const uint32_t rowadr = vsb + (uint32_t)(j * 16 + (lane & 15)) * (ALD * 2);
#pragma unroll
            for (int nd = 0; nd < 8; nd++) {
                uint32_t vbh[2], vbl[2];
                LDSM_X2_T(vbh[0], vbh[1], rowadr + nd * 16);
                LDSM_X2_T(vbl[0], vbl[1], rowadr + nd * 16 + 128);
                mma_bf16(o[nd], pah, vbl);
                mma_bf16(o[nd], pal, vbh);
                mma_bf16(o[nd], pah, vbh);
            }
        }
        __syncthreads();
    }

    // ---- epilogue ----
    float inv0 = 1.f / l0, inv1 = 1.f / l1;
    float* Og  = O + ((size_t)(b * TT + q0 + w * 16 + gid)) * CC + h * DH;
    float* Og8 = Og + (size_t)8 * CC;
#pragma unroll
    for (int nd = 0; nd < 8; nd++) {
        *(float2*)(Og  + nd * 8 + 2 * t4) =
            make_float2(o[nd][0] * inv0, o[nd][1] * inv0);
        *(float2*)(Og8 + nd * 8 + 2 * t4) =
            make_float2(o[nd][2] * inv1, o[nd][3] * inv1);
    }
}

// ---------------- launch ----------------------------------------------------
extern "C" void kernel_launch(void* const* d_in, const int* in_sizes, int n_in,
                              void* d_out, int out_size)
{
    const float* x    = (const float*)d_in[0];
    const float* Wqkv = (const float*)d_in[1];
    const float* bqkv = (const float*)d_in[2];
    const float* Wout = (const float*)d_in[3];
    const float* bout = (const float*)d_in[4];
    float* out = (float*)d_out;

    float *p_qkv, *p_q, *p_k, *p_v, *p_att, *p_wqkvt, *p_wot;
    cudaGetSymbolAddress((void**)&p_qkv,   g_qkv);
    cudaGetSymbolAddress((void**)&p_q,     g_q);
    cudaGetSymbolAddress((void**)&p_k,     g_k);
    cudaGetSymbolAddress((void**)&p_v,     g_v);
    cudaGetSymbolAddress((void**)&p_att,   g_att);
    cudaGetSymbolAddress((void**)&p_wqkvt, g_wqkvt);
    cudaGetSymbolAddress((void**)&p_wot,   g_wot);

    const int gemm_smem = 2 * 2 * GSTG * (int)sizeof(__nv_bfloat16);  // 40960 B
    cudaFuncSetAttribute(gemm_bf16x3,
                         cudaFuncAttributeMaxDynamicSharedMemorySize, gemm_smem);

    // 0) transpose weights to K-major
    transpose_k<<<dim3(3 * CC / 32, CC / 32), 256>>>(Wqkv, p_wqkvt, CC, 3 * CC);
    transpose_k<<<dim3(CC / 32, CC / 32), 256>>>(Wout, p_wot, CC, CC);

    // 1) QKV projection (3xBF16 mma)
    gemm_bf16x3<<<dim3(3 * CC / 128, BT / 128), 256, gemm_smem>>>(
        x, p_wqkvt, bqkv, p_qkv, BT, 3 * CC, CC);

    // 2) RoPE + split to [B,H,T,Dh]
    {
        int n = BB * HH * TT * 32;
        rope_split<<<n / 256, 256>>>(p_qkv, p_q, p_k, p_v);
    }

    // 3) attention (bf16x3 mma + poly exp)
    attn_mma<<<dim3(TT / 64, BB * HH), 128>>>(p_q, p_k, p_v, p_att);

    // 4) output projection (3xBF16 mma)
    gemm_bf16x3<<<dim3(CC / 128, BT / 128), 256, gemm_smem>>>(
        p_att, p_wot, bout, out, BT, CC, CC);
}

// round 5
// speedup vs baseline: 2.5860x; 1.3344x over previous
#include <cuda_runtime.h>
#include <cuda_bf16.h>
#include <cstdint>
#include <math.h>

#define BB 4
#define TT 2048
#define CC 1024
#define HH 16
#define DH 64
#define BT (BB*TT)

typedef __nv_bfloat16 bf;

// ---------------- scratch (static device globals) ---------------------------
__device__ float g_qkv[(size_t)BT * 3 * CC];
__device__ float g_wqkvt[(size_t)3 * CC * CC];
__device__ float g_wot[(size_t)CC * CC];
__device__ bf g_xh[(size_t)BT * CC],      g_xl[(size_t)BT * CC];
__device__ bf g_wqh[(size_t)3 * CC * CC], g_wql[(size_t)3 * CC * CC];
__device__ bf g_woh[(size_t)CC * CC],     g_wol[(size_t)CC * CC];
__device__ bf g_qh[(size_t)BB*HH*TT*DH],  g_ql[(size_t)BB*HH*TT*DH];
__device__ bf g_kh[(size_t)BB*HH*TT*DH],  g_kl[(size_t)BB*HH*TT*DH];
__device__ bf g_vh[(size_t)BB*HH*TT*DH],  g_vl[(size_t)BB*HH*TT*DH];
__device__ bf g_atth[(size_t)BT * CC],    g_attl[(size_t)BT * CC];

// ================= helpers ===================================================
__device__ __forceinline__ uint32_t smem_u32(const void* p) {
    uint32_t a;
    asm("{ .reg .u64 t; cvta.to.shared.u64 t, %1; cvt.u32.u64 %0, t; }"
        : "=r"(a) : "l"(p));
    return a;
}
__device__ __forceinline__ uint32_t bpack(float a, float b) {
    __nv_bfloat162 t;
    t.x = __float2bfloat16(a);
    t.y = __float2bfloat16(b);
    return *reinterpret_cast<uint32_t*>(&t);
}
__device__ __forceinline__ uint32_t bpack_lo(float a, float b, uint32_t hp) {
    __nv_bfloat162 h = *reinterpret_cast<__nv_bfloat162*>(&hp);
    return bpack(a - __bfloat162float(h.x), b - __bfloat162float(h.y));
}
__device__ __forceinline__ void cvt4(float4 v, uint2& h, uint2& l) {
    h.x = bpack(v.x, v.y);
    h.y = bpack(v.z, v.w);
    l.x = bpack_lo(v.x, v.y, h.x);
    l.y = bpack_lo(v.z, v.w, h.y);
}
__device__ __forceinline__ void mma_bf16(float* d, const uint32_t* a,
                                         uint32_t b0, uint32_t b1) {
    asm volatile(
        "mma.sync.aligned.m16n8k16.row.col.f32.bf16.bf16.f32 "
        "{%0,%1,%2,%3}, {%4,%5,%6,%7}, {%8,%9}, {%0,%1,%2,%3};"
        : "+f"(d[0]), "+f"(d[1]), "+f"(d[2]), "+f"(d[3])
        : "r"(a[0]), "r"(a[1]), "r"(a[2]), "r"(a[3]), "r"(b0), "r"(b1));
}
#define LDSM_X4(r0,r1,r2,r3,addr)                                             \
    asm volatile("ldmatrix.sync.aligned.m8n8.x4.shared.b16 {%0,%1,%2,%3}, [%4];" \
                 : "=r"(r0),"=r"(r1),"=r"(r2),"=r"(r3) : "r"(addr))
#define LDSM_X4_T(r0,r1,r2,r3,addr)                                           \
    asm volatile("ldmatrix.sync.aligned.m8n8.x4.trans.shared.b16 {%0,%1,%2,%3}, [%4];" \
                 : "=r"(r0),"=r"(r1),"=r"(r2),"=r"(r3) : "r"(addr))
#define CP16(dst, src)                                                        \
    asm volatile("cp.async.cg.shared.global [%0], [%1], 16;"                  \
                 :: "r"(dst), "l"(__cvta_generic_to_global((const void*)(src))))
#define CP_COMMIT() asm volatile("cp.async.commit_group;")
#define CP_WAIT(n)  asm volatile("cp.async.wait_group %0;" :: "n"(n))

// fast exp on FMA pipe (x <= 0)
__device__ __forceinline__ float expfast(float x) {
    float y = fmaxf(x * 1.4426950408889634f, -126.0f);
    int   ni = __float2int_rn(y);
    float f  = y - (float)ni;
    float p = 0.0013333558146428443f;
    p = fmaf(p, f, 0.009618129107628477f);
    p = fmaf(p, f, 0.05550410866482158f);
    p = fmaf(p, f, 0.2402265069591007f);
    p = fmaf(p, f, 0.6931471805599453f);
    p = fmaf(p, f, 1.0f);
    return p * __int_as_float((ni + 127) << 23);
}

// ================= small prep kernels ========================================
__global__ __launch_bounds__(256) void transpose_k(
    const float* __restrict__ W, float* __restrict__ Wt, int K, int N)
{
    __shared__ float t[32][33];
    int n0 = blockIdx.x * 32, k0 = blockIdx.y * 32;
    int lx = threadIdx.x & 31, ly = threadIdx.x >> 5;
#pragma unroll
    for (int i = 0; i < 32; i += 8)
        t[ly + i][lx] = W[(size_t)(k0 + ly + i) * N + n0 + lx];
    __syncthreads();
#pragma unroll
    for (int i = 0; i < 32; i += 8)
        Wt[(size_t)(n0 + ly + i) * K + k0 + lx] = t[lx][ly + i];
}

__global__ __launch_bounds__(256) void splitf(
    const float* __restrict__ A, bf* __restrict__ H, bf* __restrict__ L, int n4)
{
    int i = blockIdx.x * blockDim.x + threadIdx.x;
    if (i >= n4) return;
    float4 v = ((const float4*)A)[i];
    uint2 h, l;
    cvt4(v, h, l);
    ((uint2*)H)[i] = h;
    ((uint2*)L)[i] = l;
}

// ================= hi/lo bf16 GEMM (cp.async + ldmatrix) =====================
// C[M,N] = (Ah+Al)[M,K] @ (Bh+Bl)[N,K]^T + bias (3-term compensation)
// CTA 128x128, BK=32, 8 warps (32m x 64n each), double-buffered.
// stage layout (halves): Ah[128x40] @0, Al @5120, Bh @10240, Bl @15360
#define GEMM_STG 20480          // halves per stage
#define GEMM_SMEM (2 * GEMM_STG * 2)  // bytes

__global__ __launch_bounds__(256, 1) void gemm_hl(
    const bf* __restrict__ Ah, const bf* __restrict__ Al,
    const bf* __restrict__ Bh, const bf* __restrict__ Bl,
    const float* __restrict__ bias, float* __restrict__ C,
    int M, int N, int K)
{
    extern __shared__ bf dsm[];
    const uint32_t smb = smem_u32(dsm);
    const int tid  = threadIdx.x;
    const int lane = tid & 31, gid = lane >> 2, t4 = lane & 3;
    const int wid  = tid >> 5;
    const int wm   = wid & 3, wn = wid >> 2;
    const int tile_n = blockIdx.x * 128, tile_m = blockIdx.y * 128;

    const bf* srcb[4];
    srcb[0] = Ah + (size_t)tile_m * K;
    srcb[1] = Al + (size_t)tile_m * K;
    srcb[2] = Bh + (size_t)tile_n * K;
    srcb[3] = Bl + (size_t)tile_n * K;

    float acc[2][8][4];
#pragma unroll
    for (int ma = 0; ma < 2; ma++)
#pragma unroll
        for (int na = 0; na < 8; na++)
#pragma unroll
            for (int c = 0; c < 4; c++) acc[ma][na][c] = 0.f;

    const int kiters = K / 32;

    // per-lane fragment address bases (halves)
    const int a_base = (lane & 15) * 40 + (lane >> 4) * 8 + wm * 32 * 40;
    const int b_base = ((lane & 7) + ((lane >> 4) & 1) * 8) * 40 +
                       ((lane >> 3) & 1) * 8 + wn * 64 * 40 + 10240;

#define GISSUE(IT, ST)                                                        \
    do {                                                                      \
        _Pragma("unroll")                                                     \
        for (int i = 0; i < 8; i++) {                                         \
            int idx = i * 256 + tid;                                          \
            int tile = i >> 1;                                                \
            int r = (idx >> 2) & 127, ch = idx & 3;                           \
            const bf* src = srcb[tile] + (size_t)r * K + (IT) * 32 + ch * 8;  \
            uint32_t dst = smb + ((ST) * GEMM_STG + tile * 5120 +             \
                                  r * 40 + ch * 8) * 2;                       \
            CP16(dst, src);                                                   \
        }                                                                     \
        CP_COMMIT();                                                          \
    } while (0)

    GISSUE(0, 0);

    for (int it = 0; it < kiters; it++) {
        const int st = it & 1;
        if (it + 1 < kiters) {
            GISSUE(it + 1, st ^ 1);
            CP_WAIT(1);
        } else {
            CP_WAIT(0);
        }
        __syncthreads();

        const uint32_t stg = smb + (st * GEMM_STG) * 2;

        uint32_t ah[2][2][4], al[2][2][4];
#pragma unroll
        for (int ma = 0; ma < 2; ma++)
#pragma unroll
            for (int ks = 0; ks < 2; ks++) {
                uint32_t ad = stg + (a_base + ma * 640 + ks * 16) * 2;
                LDSM_X4(ah[ma][ks][0], ah[ma][ks][1], ah[ma][ks][2], ah[ma][ks][3], ad);
                LDSM_X4(al[ma][ks][0], al[ma][ks][1], al[ma][ks][2], al[ma][ks][3],
                        ad + 5120 * 2);
            }

#pragma unroll
        for (int ks = 0; ks < 2; ks++) {
#pragma unroll
            for (int nb = 0; nb < 4; nb++) {
                uint32_t bd = stg + (b_base + nb * 640 + ks * 16) * 2;
                uint32_t h0, h1, h2, h3, l0, l1, l2, l3;
                LDSM_X4(h0, h1, h2, h3, bd);
                LDSM_X4(l0, l1, l2, l3, bd + 5120 * 2);
#pragma unroll
                for (int ma = 0; ma < 2; ma++) {
                    mma_bf16(acc[ma][2*nb],   ah[ma][ks], l0, l1);
                    mma_bf16(acc[ma][2*nb],   al[ma][ks], h0, h1);
                    mma_bf16(acc[ma][2*nb],   ah[ma][ks], h0, h1);
                    mma_bf16(acc[ma][2*nb+1], ah[ma][ks], l2, l3);
                    mma_bf16(acc[ma][2*nb+1], al[ma][ks], h2, h3);
                    mma_bf16(acc[ma][2*nb+1], ah[ma][ks], h2, h3);
                }
            }
        }
        __syncthreads();
    }
#undef GISSUE

#pragma unroll
    for (int ma = 0; ma < 2; ma++) {
        const int r0 = tile_m + wm * 32 + ma * 16 + gid;
#pragma unroll
        for (int na = 0; na < 8; na++) {
            const int c0 = tile_n + wn * 64 + na * 8 + t4 * 2;
            float2 bv = *(const float2*)(bias + c0);
            *(float2*)(C + (size_t)r0 * N + c0) =
                make_float2(acc[ma][na][0] + bv.x, acc[ma][na][1] + bv.y);
            *(float2*)(C + (size_t)(r0 + 8) * N + c0) =
                make_float2(acc[ma][na][2] + bv.x, acc[ma][na][3] + bv.y);
        }
    }
}

// ================= RoPE + split to bf16 hi/lo ================================
__global__ __launch_bounds__(256) void rope_split(
    const float* __restrict__ qkv,
    bf* __restrict__ Qh, bf* __restrict__ Ql,
    bf* __restrict__ Kh, bf* __restrict__ Kl,
    bf* __restrict__ Vh, bf* __restrict__ Vl)
{
    int idx = blockIdx.x * blockDim.x + threadIdx.x;
    if (idx >= BB * HH * TT * 32) return;
    int j = idx & 31;
    int t = (idx >> 5) & (TT - 1);
    int h = (idx >> 16) & (HH - 1);
    int b = idx >> 20;

    const float* base = qkv + ((size_t)(b * TT + t)) * (3 * CC) + h * DH;

    float invf = exp2f(-(float)j * 0.41524101186f);
    float ang  = (float)t * invf;
    float sn, cs;
    sincosf(ang, &sn, &cs);

    size_t o = ((size_t)((b * HH + h) * TT + t)) * DH;

    float q1 = base[j],          q2 = base[j + 32];
    float k1 = base[CC + j],     k2 = base[CC + j + 32];
    float v1 = base[2 * CC + j], v2 = base[2 * CC + j + 32];

    float qa = (q1 * cs - q2 * sn) * 0.125f;   // fold 1/sqrt(64)
    float qb = (q2 * cs + q1 * sn) * 0.125f;
    float ka = k1 * cs - k2 * sn;
    float kb = k2 * cs + k1 * sn;

#define SPL(arrH, arrL, pos, val)                                            \
    { bf _h = __float2bfloat16(val);                                         \
      arrH[pos] = _h;                                                        \
      arrL[pos] = __float2bfloat16((val) - __bfloat162float(_h)); }
    SPL(Qh, Ql, o + j,      qa);
    SPL(Qh, Ql, o + j + 32, qb);
    SPL(Kh, Kl, o + j,      ka);
    SPL(Kh, Kl, o + j + 32, kb);
    SPL(Vh, Vl, o + j,      v1);
    SPL(Vh, Vl, o + j + 32, v2);
#undef SPL
}

// ================= FA2 attention: bf16 hi/lo, cp.async + ldmatrix ============
// CTA: 128 q rows, 256 threads (8 warps x 16q). 64-key tiles, double-buffered.
// smem (halves): Qh[128x72]@0, Ql@9216; stages@18432+st*18432:
//   per stage Kh@0, Kl@4608, Vh@9216, Vl@13824 (each 64x72)
#define ASTG  18432
#define ASMEM ((18432 + 2 * 18432) * 2)

__global__ __launch_bounds__(256, 1) void attn_hl(
    const bf* __restrict__ Qh, const bf* __restrict__ Ql,
    const bf* __restrict__ Kh, const bf* __restrict__ Kl,
    const bf* __restrict__ Vh, const bf* __restrict__ Vl,
    bf* __restrict__ AttH, bf* __restrict__ AttL)
{
    extern __shared__ bf dsm[];
    const uint32_t smb = smem_u32(dsm);
    const int tid = threadIdx.x;
    const int lane = tid & 31, gid = lane >> 2, t4 = lane & 3;
    const int w = tid >> 5;
    const int bh = blockIdx.y;
    const int q0 = blockIdx.x * 128;
    const int b = bh >> 4, h = bh & 15;

    const size_t hoff = (size_t)bh * TT * DH;
    const bf* kvsrc[4];
    kvsrc[0] = Kh + hoff;
    kvsrc[1] = Kl + hoff;
    kvsrc[2] = Vh + hoff;
    kvsrc[3] = Vl + hoff;

#define AISSUE(KB, ST)                                                       \
    do {                                                                     \
        _Pragma("unroll")                                                    \
        for (int i = 0; i < 8; i++) {                                        \
            int idx = i * 256 + tid;                                         \
            int tile = i >> 1;                                               \
            int r = (idx >> 3) & 63, ch = idx & 7;                           \
            const bf* src = kvsrc[tile] + (size_t)((KB) + r) * DH + ch * 8;  \
            uint32_t dst = smb + (18432 + (ST) * ASTG + tile * 4608 +        \
                                  r * 72 + ch * 8) * 2;                      \
            CP16(dst, src);                                                  \
        }                                                                    \
        CP_COMMIT();                                                         \
    } while (0)

    // ---- stage Q ----
    {
        const bf* qsrc[2];
        qsrc[0] = Qh + hoff + (size_t)q0 * DH;
        qsrc[1] = Ql + hoff + (size_t)q0 * DH;
#pragma unroll
        for (int i = 0; i < 8; i++) {
            int idx = i * 256 + tid;
            int arr = i >> 2;                       // idx>>10
            int r = (idx >> 3) & 127, ch = idx & 7;
            const bf* src = qsrc[arr] + (size_t)r * DH + ch * 8;
            uint32_t dst = smb + (arr * 9216 + r * 72 + ch * 8) * 2;
            CP16(dst, src);
        }
        CP_COMMIT();
    }
    AISSUE(0, 0);
    CP_WAIT(1);           // Q complete
    __syncthreads();

    // ---- Q fragments ----
    uint32_t qhf[4][4], qlf[4][4];
    {
        const uint32_t qb = smb + ((w * 16 + (lane & 15)) * 72 + (lane >> 4) * 8) * 2;
#pragma unroll
        for (int ks = 0; ks < 4; ks++) {
            LDSM_X4(qhf[ks][0], qhf[ks][1], qhf[ks][2], qhf[ks][3], qb + ks * 32);
            LDSM_X4(qlf[ks][0], qlf[ks][1], qlf[ks][2], qlf[ks][3],
                    qb + ks * 32 + 9216 * 2);
        }
    }

    float m0 = -1e30f, m1 = -1e30f, l0 = 0.f, l1 = 0.f;
    float o[8][4];
#pragma unroll
    for (int nd = 0; nd < 8; nd++)
#pragma unroll
        for (int c = 0; c < 4; c++) o[nd][c] = 0.f;

    const int k_base = ((lane & 7) + ((lane >> 4) & 1) * 8) * 72 +
                       ((lane >> 3) & 1) * 8;
    const int v_base = ((lane & 7) + ((lane >> 3) & 1) * 8) * 72 +
                       ((lane >> 4) & 1) * 8;

    const int ntiles = TT / 64;
    for (int it = 0; it < ntiles; it++) {
        const int st = it & 1;
        if (it + 1 < ntiles) {
            AISSUE((it + 1) * 64, st ^ 1);
            CP_WAIT(1);
        } else {
            CP_WAIT(0);
        }
        __syncthreads();

        const uint32_t stg = smb + (18432 + st * ASTG) * 2;

        // ---- S = Q @ K^T ----
        float s[8][4];
#pragma unroll
        for (int n = 0; n < 8; n++)
#pragma unroll
            for (int c = 0; c < 4; c++) s[n][c] = 0.f;

#pragma unroll
        for (int ks = 0; ks < 4; ks++) {
#pragma unroll
            for (int nb = 0; nb < 4; nb++) {
                uint32_t kd = stg + (nb * 1152 + k_base + ks * 16) * 2;
                uint32_t h0, h1, h2, h3, lo0, lo1, lo2, lo3;
                LDSM_X4(h0, h1, h2, h3, kd);
                LDSM_X4(lo0, lo1, lo2, lo3, kd + 4608 * 2);
                mma_bf16(s[2*nb],   qhf[ks], lo0, lo1);
                mma_bf16(s[2*nb],   qlf[ks], h0, h1);
                mma_bf16(s[2*nb],   qhf[ks], h0, h1);
                mma_bf16(s[2*nb+1], qhf[ks], lo2, lo3);
                mma_bf16(s[2*nb+1], qlf[ks], h2, h3);
                mma_bf16(s[2*nb+1], qhf[ks], h2, h3);
            }
        }

        // ---- online softmax (rows gid, gid+8) ----
        float mx0 = -1e30f, mx1 = -1e30f;
#pragma unroll
        for (int n = 0; n < 8; n++) {
            mx0 = fmaxf(mx0, fmaxf(s[n][0], s[n][1]));
            mx1 = fmaxf(mx1, fmaxf(s[n][2], s[n][3]));
        }
        mx0 = fmaxf(mx0, __shfl_xor_sync(0xffffffffu, mx0, 1));
        mx0 = fmaxf(mx0, __shfl_xor_sync(0xffffffffu, mx0, 2));
        mx1 = fmaxf(mx1, __shfl_xor_sync(0xffffffffu, mx1, 1));
        mx1 = fmaxf(mx1, __shfl_xor_sync(0xffffffffu, mx1, 2));

        float m0n = fmaxf(m0, mx0), m1n = fmaxf(m1, mx1);
        float c0 = expfast(m0 - m0n), c1 = expfast(m1 - m1n);
        float s0 = 0.f, s1 = 0.f;
#pragma unroll
        for (int n = 0; n < 8; n++) {
            s[n][0] = expfast(s[n][0] - m0n); s0 += s[n][0];
            s[n][1] = expfast(s[n][1] - m0n); s0 += s[n][1];
            s[n][2] = expfast(s[n][2] - m1n); s1 += s[n][2];
            s[n][3] = expfast(s[n][3] - m1n); s1 += s[n][3];
        }
        s0 += __shfl_xor_sync(0xffffffffu, s0, 1);
        s0 += __shfl_xor_sync(0xffffffffu, s0, 2);
        s1 += __shfl_xor_sync(0xffffffffu, s1, 1);
        s1 += __shfl_xor_sync(0xffffffffu, s1, 2);
        l0 = l0 * c0 + s0;
        l1 = l1 * c1 + s1;
        m0 = m0n; m1 = m1n;
#pragma unroll
        for (int nd = 0; nd < 8; nd++) {
            o[nd][0] *= c0; o[nd][1] *= c0;
            o[nd][2] *= c1; o[nd][3] *= c1;
        }

        // ---- O += P @ V ----
#pragma unroll
        for (int ksj = 0; ksj < 4; ksj++) {
            uint32_t pah[4], pal[4];
            pah[0] = bpack(s[2*ksj][0],   s[2*ksj][1]);
            pah[1] = bpack(s[2*ksj][2],   s[2*ksj][3]);
            pah[2] = bpack(s[2*ksj+1][0], s[2*ksj+1][1]);
            pah[3] = bpack(s[2*ksj+1][2], s[2*ksj+1][3]);
            pal[0] = bpack_lo(s[2*ksj][0],   s[2*ksj][1],   pah[0]);
            pal[1] = bpack_lo(s[2*ksj][2],   s[2*ksj][3],   pah[1]);
            pal[2] = bpack_lo(s[2*ksj+1][0], s[2*ksj+1][1], pah[2]);
            pal[3] = bpack_lo(s[2*ksj+1][2], s[2*ksj+1][3], pah[3]);

#pragma unroll
            for (int dbp = 0; dbp < 4; dbp++) {
                uint32_t vd = stg + (9216 + ksj * 1152 + v_base + dbp * 16) * 2;
                uint32_t h0, h1, h2, h3, lo0, lo1, lo2, lo3;
                LDSM_X4_T(h0, h1, h2, h3, vd);
                LDSM_X4_T(lo0, lo1, lo2, lo3, vd + 4608 * 2);
                mma_bf16(o[2*dbp],   pah, lo0, lo1);
                mma_bf16(o[2*dbp],   pal, h0, h1);
                mma_bf16(o[2*dbp],   pah, h0, h1);
                mma_bf16(o[2*dbp+1], pah, lo2, lo3);
                mma_bf16(o[2*dbp+1], pal, h2, h3);
                mma_bf16(o[2*dbp+1], pah, h2, h3);
            }
        }
        __syncthreads();
    }
#undef AISSUE

    // ---- epilogue: write att as bf16 hi/lo [B,T,C] ----
    float inv0 = 1.f / l0, inv1 = 1.f / l1;
    size_t row0 = (size_t)(b * TT + q0 + w * 16 + gid);
    size_t row1 = row0 + 8;
#pragma unroll
    for (int nd = 0; nd < 8; nd++) {
        int c = h * DH + nd * 8 + 2 * t4;
        float a0 = o[nd][0] * inv0, a1 = o[nd][1] * inv0;
        uint32_t hh = bpack(a0, a1);
        *(uint32_t*)(AttH + row0 * CC + c) = hh;
        *(uint32_t*)(AttL + row0 * CC + c) = bpack_lo(a0, a1, hh);
        float b0 = o[nd][2] * inv1, b1 = o[nd][3] * inv1;
        uint32_t hh2 = bpack(b0, b1);
        *(uint32_t*)(AttH + row1 * CC + c) = hh2;
        *(uint32_t*)(AttL + row1 * CC + c) = bpack_lo(b0, b1, hh2);
    }
}

// ---------------- launch ----------------------------------------------------
extern "C" void kernel_launch(void* const* d_in, const int* in_sizes, int n_in,
                              void* d_out, int out_size)
{
    const float* x    = (const float*)d_in[0];
    const float* Wqkv = (const float*)d_in[1];
    const float* bqkv = (const float*)d_in[2];
    const float* Wout = (const float*)d_in[3];
    const float* bout = (const float*)d_in[4];
    float* out = (float*)d_out;

    float *p_qkv, *p_wqkvt, *p_wot;
    bf *p_xh, *p_xl, *p_wqh, *p_wql, *p_woh, *p_wol;
    bf *p_qh, *p_ql, *p_kh, *p_kl, *p_vh, *p_vl, *p_atth, *p_attl;
    cudaGetSymbolAddress((void**)&p_qkv,   g_qkv);
    cudaGetSymbolAddress((void**)&p_wqkvt, g_wqkvt);
    cudaGetSymbolAddress((void**)&p_wot,   g_wot);
    cudaGetSymbolAddress((void**)&p_xh,    g_xh);
    cudaGetSymbolAddress((void**)&p_xl,    g_xl);
    cudaGetSymbolAddress((void**)&p_wqh,   g_wqh);
    cudaGetSymbolAddress((void**)&p_wql,   g_wql);
    cudaGetSymbolAddress((void**)&p_woh,   g_woh);
    cudaGetSymbolAddress((void**)&p_wol,   g_wol);
    cudaGetSymbolAddress((void**)&p_qh,    g_qh);
    cudaGetSymbolAddress((void**)&p_ql,    g_ql);
    cudaGetSymbolAddress((void**)&p_kh,    g_kh);
    cudaGetSymbolAddress((void**)&p_kl,    g_kl);
    cudaGetSymbolAddress((void**)&p_vh,    g_vh);
    cudaGetSymbolAddress((void**)&p_vl,    g_vl);
    cudaGetSymbolAddress((void**)&p_atth,  g_atth);
    cudaGetSymbolAddress((void**)&p_attl,  g_attl);

    cudaFuncSetAttribute(gemm_hl,
                         cudaFuncAttributeMaxDynamicSharedMemorySize, GEMM_SMEM);
    cudaFuncSetAttribute(attn_hl,
                         cudaFuncAttributeMaxDynamicSharedMemorySize, ASMEM);

    // 0) weight transposes + hi/lo splits
    transpose_k<<<dim3(3 * CC / 32, CC / 32), 256>>>(Wqkv, p_wqkvt, CC, 3 * CC);
    transpose_k<<<dim3(CC / 32, CC / 32), 256>>>(Wout, p_wot, CC, CC);
    splitf<<<(BT * CC / 4) / 256, 256>>>(x, p_xh, p_xl, BT * CC / 4);
    splitf<<<(3 * CC * CC / 4) / 256, 256>>>(p_wqkvt, p_wqh, p_wql, 3 * CC * CC / 4);
    splitf<<<(CC * CC / 4) / 256, 256>>>(p_wot, p_woh, p_wol, CC * CC / 4);

    // 1) QKV projection
    gemm_hl<<<dim3(3 * CC / 128, BT / 128), 256, GEMM_SMEM>>>(
        p_xh, p_xl, p_wqh, p_wql, bqkv, p_qkv, BT, 3 * CC, CC);

    // 2) RoPE + split to bf16 hi/lo [B,H,T,Dh]
    rope_split<<<(BB * HH * TT * 32) / 256, 256>>>(
        p_qkv, p_qh, p_ql, p_kh, p_kl, p_vh, p_vl);

    // 3) attention
    attn_hl<<<dim3(TT / 128, BB * HH), 256, ASMEM>>>(
        p_qh, p_ql, p_kh, p_kl, p_vh, p_vl, p_atth, p_attl);

    // 4) output projection
    gemm_hl<<<dim3(CC / 128, BT / 128), 256, GEMM_SMEM>>>(
        p_atth, p_attl, p_woh, p_wol, bout, out, BT, CC, CC);
}

// round 6
// speedup vs baseline: 2.6366x; 1.0196x over previous
#include <cuda_runtime.h>
#include <cuda_bf16.h>
#include <cstdint>
#include <math.h>

#define BB 4
#define TT 2048
#define CC 1024
#define HH 16
#define DH 64
#define BT (BB*TT)

typedef __nv_bfloat16 bf;

// ---------------- scratch (static device globals) ---------------------------
__device__ bf g_xh[(size_t)BT * CC],      g_xl[(size_t)BT * CC];
__device__ bf g_wqh[(size_t)3 * CC * CC], g_wql[(size_t)3 * CC * CC];
__device__ bf g_woh[(size_t)CC * CC],     g_wol[(size_t)CC * CC];
__device__ bf g_qh[(size_t)BB*HH*TT*DH],  g_ql[(size_t)BB*HH*TT*DH];
__device__ bf g_kh[(size_t)BB*HH*TT*DH],  g_kl[(size_t)BB*HH*TT*DH];
__device__ bf g_vh[(size_t)BB*HH*TT*DH],  g_vl[(size_t)BB*HH*TT*DH];
__device__ bf g_atth[(size_t)BT * CC],    g_attl[(size_t)BT * CC];
__device__ float2 g_rope[(size_t)TT * 32];

// ================= helpers ===================================================
__device__ __forceinline__ uint32_t smem_u32(const void* p) {
    uint32_t a;
    asm("{ .reg .u64 t; cvta.to.shared.u64 t, %1; cvt.u32.u64 %0, t; }"
        : "=r"(a) : "l"(p));
    return a;
}
__device__ __forceinline__ uint32_t bpack(float a, float b) {
    __nv_bfloat162 t;
    t.x = __float2bfloat16(a);
    t.y = __float2bfloat16(b);
    return *reinterpret_cast<uint32_t*>(&t);
}
__device__ __forceinline__ uint32_t bpack_lo(float a, float b, uint32_t hp) {
    __nv_bfloat162 h = *reinterpret_cast<__nv_bfloat162*>(&hp);
    return bpack(a - __bfloat162float(h.x), b - __bfloat162float(h.y));
}
__device__ __forceinline__ void cvt4(float4 v, uint2& h, uint2& l) {
    h.x = bpack(v.x, v.y);
    h.y = bpack(v.z, v.w);
    l.x = bpack_lo(v.x, v.y, h.x);
    l.y = bpack_lo(v.z, v.w, h.y);
}
__device__ __forceinline__ void mma_bf16(float* d, const uint32_t* a,
                                         uint32_t b0, uint32_t b1) {
    asm volatile(
        "mma.sync.aligned.m16n8k16.row.col.f32.bf16.bf16.f32 "
        "{%0,%1,%2,%3}, {%4,%5,%6,%7}, {%8,%9}, {%0,%1,%2,%3};"
        : "+f"(d[0]), "+f"(d[1]), "+f"(d[2]), "+f"(d[3])
        : "r"(a[0]), "r"(a[1]), "r"(a[2]), "r"(a[3]), "r"(b0), "r"(b1));
}
#define LDSM_X4(r0,r1,r2,r3,addr)                                             \
    asm volatile("ldmatrix.sync.aligned.m8n8.x4.shared.b16 {%0,%1,%2,%3}, [%4];" \
                 : "=r"(r0),"=r"(r1),"=r"(r2),"=r"(r3) : "r"(addr))
#define LDSM_X4_T(r0,r1,r2,r3,addr)                                           \
    asm volatile("ldmatrix.sync.aligned.m8n8.x4.trans.shared.b16 {%0,%1,%2,%3}, [%4];" \
                 : "=r"(r0),"=r"(r1),"=r"(r2),"=r"(r3) : "r"(addr))
#define CP16(dst, src)                                                        \
    asm volatile("cp.async.cg.shared.global [%0], [%1], 16;"                  \
                 :: "r"(dst), "l"(__cvta_generic_to_global((const void*)(src))))
#define CP_COMMIT() asm volatile("cp.async.commit_group;")
#define CP_WAIT(n)  asm volatile("cp.async.wait_group %0;" :: "n"(n))

// fast exp on FMA pipe (x <= 0)
__device__ __forceinline__ float expfast(float x) {
    float y = fmaxf(x * 1.4426950408889634f, -126.0f);
    int   ni = __float2int_rn(y);
    float f  = y - (float)ni;
    float p = 0.0013333558146428443f;
    p = fmaf(p, f, 0.009618129107628477f);
    p = fmaf(p, f, 0.05550410866482158f);
    p = fmaf(p, f, 0.2402265069591007f);
    p = fmaf(p, f, 0.6931471805599453f);
    p = fmaf(p, f, 1.0f);
    return p * __int_as_float((ni + 127) << 23);
}

// ================= prep kernels ==============================================
// W[K,N] -> hi/lo bf16 of W^T [N,K]
__global__ __launch_bounds__(256) void transpose_split(
    const float* __restrict__ W, bf* __restrict__ H, bf* __restrict__ L,
    int K, int N)
{
    __shared__ float t[32][33];
    int n0 = blockIdx.x * 32, k0 = blockIdx.y * 32;
    int lx = threadIdx.x & 31, ly = threadIdx.x >> 5;
#pragma unroll
    for (int i = 0; i < 32; i += 8)
        t[ly + i][lx] = W[(size_t)(k0 + ly + i) * N + n0 + lx];
    __syncthreads();
#pragma unroll
    for (int i = 0; i < 32; i += 8) {
        float v = t[lx][ly + i];
        bf h = __float2bfloat16(v);
        size_t o = (size_t)(n0 + ly + i) * K + k0 + lx;
        H[o] = h;
        L[o] = __float2bfloat16(v - __bfloat162float(h));
    }
}

__global__ __launch_bounds__(256) void splitf(
    const float* __restrict__ A, bf* __restrict__ H, bf* __restrict__ L, int n4)
{
    int i = blockIdx.x * blockDim.x + threadIdx.x;
    if (i >= n4) return;
    float4 v = ((const float4*)A)[i];
    uint2 h, l;
    cvt4(v, h, l);
    ((uint2*)H)[i] = h;
    ((uint2*)L)[i] = l;
}

__global__ __launch_bounds__(256) void rope_table(float2* __restrict__ T)
{
    int i = blockIdx.x * 256 + threadIdx.x;          // 65536
    int t = i >> 5, j = i & 31;
    float invf = exp2f(-(float)j * 0.41524101186f);
    float sn, cs;
    sincosf((float)t * invf, &sn, &cs);
    T[i] = make_float2(cs, sn);
}

// ================= hi/lo bf16 GEMM (3-stage cp.async + ldmatrix) =============
// C = (Ah+Al)[M,K] @ (Bh+Bl)[N,K]^T + bias (3-term compensation)
// CTA 128x128, BK=32, 8 warps (32m x 64n), 3-stage pipeline.
// FR=1: fused RoPE + hi/lo-split epilogue writing Q/K/V [B,H,T,Dh].
#define GEMM_STG 20480                    // halves per stage
#define GEMM_SMEM (3 * GEMM_STG * 2)      // bytes

template <int FR>
__global__ __launch_bounds__(256, 1) void gemm_hl(
    const bf* __restrict__ Ah, const bf* __restrict__ Al,
    const bf* __restrict__ Bh, const bf* __restrict__ Bl,
    const float* __restrict__ bias, float* __restrict__ C,
    const float2* __restrict__ ropeT,
    bf* __restrict__ Qh, bf* __restrict__ Ql,
    bf* __restrict__ Kh, bf* __restrict__ Kl,
    bf* __restrict__ Vh, bf* __restrict__ Vl,
    int M, int N, int K)
{
    extern __shared__ bf dsm[];
    const uint32_t smb = smem_u32(dsm);
    const int tid  = threadIdx.x;
    const int lane = tid & 31, gid = lane >> 2, t4 = lane & 3;
    const int wid  = tid >> 5;
    const int wm   = wid & 3, wn = wid >> 2;
    const int tile_n = blockIdx.x * 128, tile_m = blockIdx.y * 128;

    const bf* srcb[4];
    srcb[0] = Ah + (size_t)tile_m * K;
    srcb[1] = Al + (size_t)tile_m * K;
    srcb[2] = Bh + (size_t)tile_n * K;
    srcb[3] = Bl + (size_t)tile_n * K;

    float acc[2][8][4];
#pragma unroll
    for (int ma = 0; ma < 2; ma++)
#pragma unroll
        for (int na = 0; na < 8; na++)
#pragma unroll
            for (int c = 0; c < 4; c++) acc[ma][na][c] = 0.f;

    const int kiters = K / 32;

    const int a_base = (lane & 15) * 40 + (lane >> 4) * 8 + wm * 32 * 40;
    const int b_base = ((lane & 7) + ((lane >> 4) & 1) * 8) * 40 +
                       ((lane >> 3) & 1) * 8 + wn * 64 * 40 + 10240;

#define GISSUE(IT, ST)                                                        \
    do {                                                                      \
        _Pragma("unroll")                                                     \
        for (int i = 0; i < 8; i++) {                                         \
            int idx = i * 256 + tid;                                          \
            int tile = i >> 1;                                                \
            int r = (idx >> 2) & 127, ch = idx & 3;                           \
            const bf* src = srcb[tile] + (size_t)r * K + (IT) * 32 + ch * 8;  \
            uint32_t dst = smb + ((ST) * GEMM_STG + tile * 5120 +             \
                                  r * 40 + ch * 8) * 2;                       \
            CP16(dst, src);                                                   \
        }                                                                     \
        CP_COMMIT();                                                          \
    } while (0)

    GISSUE(0, 0);
    GISSUE(1, 1);

    for (int it = 0; it < kiters; it++) {
        if (it + 1 < kiters) { CP_WAIT(1); } else { CP_WAIT(0); }
        __syncthreads();
        if (it + 2 < kiters) {
            const int st2 = (it + 2) % 3;
            GISSUE(it + 2, st2);
        }

        const uint32_t stg = smb + ((it % 3) * GEMM_STG) * 2;

#pragma unroll
        for (int ks = 0; ks < 2; ks++) {
            uint32_t ah[2][4], al[2][4];
#pragma unroll
            for (int ma = 0; ma < 2; ma++) {
                uint32_t ad = stg + (a_base + ma * 640 + ks * 16) * 2;
                LDSM_X4(ah[ma][0], ah[ma][1], ah[ma][2], ah[ma][3], ad);
                LDSM_X4(al[ma][0], al[ma][1], al[ma][2], al[ma][3],
                        ad + 5120 * 2);
            }
            uint32_t bh[4][4], bl[4][4];
#pragma unroll
            for (int nb = 0; nb < 4; nb++) {
                uint32_t bd = stg + (b_base + nb * 640 + ks * 16) * 2;
                LDSM_X4(bh[nb][0], bh[nb][1], bh[nb][2], bh[nb][3], bd);
                LDSM_X4(bl[nb][0], bl[nb][1], bl[nb][2], bl[nb][3],
                        bd + 5120 * 2);
            }
#pragma unroll
            for (int nb = 0; nb < 4; nb++)
#pragma unroll
                for (int ma = 0; ma < 2; ma++) {
                    mma_bf16(acc[ma][2*nb],   ah[ma], bl[nb][0], bl[nb][1]);
                    mma_bf16(acc[ma][2*nb],   al[ma], bh[nb][0], bh[nb][1]);
                    mma_bf16(acc[ma][2*nb],   ah[ma], bh[nb][0], bh[nb][1]);
                    mma_bf16(acc[ma][2*nb+1], ah[ma], bl[nb][2], bl[nb][3]);
                    mma_bf16(acc[ma][2*nb+1], al[ma], bh[nb][2], bh[nb][3]);
                    mma_bf16(acc[ma][2*nb+1], ah[ma], bh[nb][2], bh[nb][3]);
                }
        }
    }
#undef GISSUE

    if (FR == 0) {
        // ---- standard epilogue: bias + fp32 store ----
#pragma unroll
        for (int ma = 0; ma < 2; ma++) {
            const int r0 = tile_m + wm * 32 + ma * 16 + gid;
#pragma unroll
            for (int na = 0; na < 8; na++) {
                const int c0 = tile_n + wn * 64 + na * 8 + t4 * 2;
                float2 bv = *(const float2*)(bias + c0);
                *(float2*)(C + (size_t)r0 * N + c0) =
                    make_float2(acc[ma][na][0] + bv.x, acc[ma][na][1] + bv.y);
                *(float2*)(C + (size_t)(r0 + 8) * N + c0) =
                    make_float2(acc[ma][na][2] + bv.x, acc[ma][na][3] + bv.y);
            }
        }
    } else {
        // ---- fused epilogue: bias + RoPE + hi/lo split -> [B,H,T,Dh] ----
        const int win = tile_n + wn * 64;         // 64-aligned: one (type, head)
        const int typ = win >> 10;                // 0=q 1=k 2=v
        const int hd  = (win & 1023) >> 6;
        bf* OH = (typ == 0) ? Qh : (typ == 1) ? Kh : Vh;
        bf* OL = (typ == 0) ? Ql : (typ == 1) ? Kl : Vl;
        const float scale = (typ == 0) ? 0.125f : 1.f;

#pragma unroll
        for (int ma = 0; ma < 2; ma++) {
#pragma unroll
            for (int rh = 0; rh < 2; rh++) {
                const int row = tile_m + wm * 32 + ma * 16 + gid + rh * 8;
                const int bb = row >> 11, tt = row & 2047;
                bf* obase = OH + ((size_t)(bb * HH + hd) * TT + tt) * DH;
                bf* obasl = OL + ((size_t)(bb * HH + hd) * TT + tt) * DH;
#pragma unroll
                for (int na = 0; na < 4; na++) {
                    const int j0 = na * 8 + t4 * 2;
                    const int c0 = win + j0;
                    float a0 = acc[ma][na][2*rh+0]     + bias[c0];
                    float a1 = acc[ma][na][2*rh+1]     + bias[c0 + 1];
                    float b0 = acc[ma][na+4][2*rh+0]   + bias[c0 + 32];
                    float b1 = acc[ma][na+4][2*rh+1]   + bias[c0 + 33];
                    float2 cs0 = make_float2(1.f, 0.f), cs1 = cs0;
                    if (typ < 2) {
                        cs0 = ropeT[tt * 32 + j0];
                        cs1 = ropeT[tt * 32 + j0 + 1];
                    }
                    float o0 = (a0 * cs0.x - b0 * cs0.y) * scale;
                    float p0 = (b0 * cs0.x + a0 * cs0.y) * scale;
                    float o1 = (a1 * cs1.x - b1 * cs1.y) * scale;
                    float p1 = (b1 * cs1.x + a1 * cs1.y) * scale;
                    uint32_t h0 = bpack(o0, o1);
                    *(uint32_t*)(obase + j0) = h0;
                    *(uint32_t*)(obasl + j0) = bpack_lo(o0, o1, h0);
                    uint32_t h1 = bpack(p0, p1);
                    *(uint32_t*)(obase + j0 + 32) = h1;
                    *(uint32_t*)(obasl + j0 + 32) = bpack_lo(p0, p1, h1);
                }
            }
        }
    }
}

// ================= FA2 attention: bf16 hi/lo, cp.async + ldmatrix ============
#define ASTG  18432
#define ASMEM ((18432 + 2 * 18432) * 2)

__global__ __launch_bounds__(256, 1) void attn_hl(
    const bf* __restrict__ Qh, const bf* __restrict__ Ql,
    const bf* __restrict__ Kh, const bf* __restrict__ Kl,
    const bf* __restrict__ Vh, const bf* __restrict__ Vl,
    bf* __restrict__ AttH, bf* __restrict__ AttL)
{
    extern __shared__ bf dsm[];
    const uint32_t smb = smem_u32(dsm);
    const int tid = threadIdx.x;
    const int lane = tid & 31, gid = lane >> 2, t4 = lane & 3;
    const int w = tid >> 5;
    const int bh = blockIdx.y;
    const int q0 = blockIdx.x * 128;
    const int b = bh >> 4, h = bh & 15;

    const size_t hoff = (size_t)bh * TT * DH;
    const bf* kvsrc[4];
    kvsrc[0] = Kh + hoff;
    kvsrc[1] = Kl + hoff;
    kvsrc[2] = Vh + hoff;
    kvsrc[3] = Vl + hoff;

#define AISSUE(KB, ST)                                                       \
    do {                                                                     \
        _Pragma("unroll")                                                    \
        for (int i = 0; i < 8; i++) {                                        \
            int idx = i * 256 + tid;                                         \
            int tile = i >> 1;                                               \
            int r = (idx >> 3) & 63, ch = idx & 7;                           \
            const bf* src = kvsrc[tile] + (size_t)((KB) + r) * DH + ch * 8;  \
            uint32_t dst = smb + (18432 + (ST) * ASTG + tile * 4608 +        \
                                  r * 72 + ch * 8) * 2;                      \
            CP16(dst, src);                                                  \
        }                                                                    \
        CP_COMMIT();                                                         \
    } while (0)

    // ---- stage Q ----
    {
        const bf* qsrc[2];
        qsrc[0] = Qh + hoff + (size_t)q0 * DH;
        qsrc[1] = Ql + hoff + (size_t)q0 * DH;
#pragma unroll
        for (int i = 0; i < 8; i++) {
            int idx = i * 256 + tid;
            int arr = i >> 2;
            int r = (idx >> 3) & 127, ch = idx & 7;
            const bf* src = qsrc[arr] + (size_t)r * DH + ch * 8;
            uint32_t dst = smb + (arr * 9216 + r * 72 + ch * 8) * 2;
            CP16(dst, src);
        }
        CP_COMMIT();
    }
    AISSUE(0, 0);
    CP_WAIT(1);
    __syncthreads();

    uint32_t qhf[4][4], qlf[4][4];
    {
        const uint32_t qb = smb + ((w * 16 + (lane & 15)) * 72 + (lane >> 4) * 8) * 2;
#pragma unroll
        for (int ks = 0; ks < 4; ks++) {
            LDSM_X4(qhf[ks][0], qhf[ks][1], qhf[ks][2], qhf[ks][3], qb + ks * 32);
            LDSM_X4(qlf[ks][0], qlf[ks][1], qlf[ks][2], qlf[ks][3],
                    qb + ks * 32 + 9216 * 2);
        }
    }

    float m0 = -1e30f, m1 = -1e30f, l0 = 0.f, l1 = 0.f;
    float o[8][4];
#pragma unroll
    for (int nd = 0; nd < 8; nd++)
#pragma unroll
        for (int c = 0; c < 4; c++) o[nd][c] = 0.f;

    const int k_base = ((lane & 7) + ((lane >> 4) & 1) * 8) * 72 +
                       ((lane >> 3) & 1) * 8;
    const int v_base = ((lane & 7) + ((lane >> 3) & 1) * 8) * 72 +
                       ((lane >> 4) & 1) * 8;

    const int ntiles = TT / 64;
    for (int it = 0; it < ntiles; it++) {
        const int st = it & 1;
        if (it + 1 < ntiles) {
            AISSUE((it + 1) * 64, st ^ 1);
            CP_WAIT(1);
        } else {
            CP_WAIT(0);
        }
        __syncthreads();

        const uint32_t stg = smb + (18432 + st * ASTG) * 2;

        float s[8][4];
#pragma unroll
        for (int n = 0; n < 8; n++)
#pragma unroll
            for (int c = 0; c < 4; c++) s[n][c] = 0.f;

#pragma unroll
        for (int ks = 0; ks < 4; ks++) {
#pragma unroll
            for (int nb = 0; nb < 4; nb++) {
                uint32_t kd = stg + (nb * 1152 + k_base + ks * 16) * 2;
                uint32_t h0, h1, h2, h3, lo0, lo1, lo2, lo3;
                LDSM_X4(h0, h1, h2, h3, kd);
                LDSM_X4(lo0, lo1, lo2, lo3, kd + 4608 * 2);
                mma_bf16(s[2*nb],   qhf[ks], lo0, lo1);
                mma_bf16(s[2*nb],   qlf[ks], h0, h1);
                mma_bf16(s[2*nb],   qhf[ks], h0, h1);
                mma_bf16(s[2*nb+1], qhf[ks], lo2, lo3);
                mma_bf16(s[2*nb+1], qlf[ks], h2, h3);
                mma_bf16(s[2*nb+1], qhf[ks], h2, h3);
            }
        }

        float mx0 = -1e30f, mx1 = -1e30f;
#pragma unroll
        for (int n = 0; n < 8; n++) {
            mx0 = fmaxf(mx0, fmaxf(s[n][0], s[n][1]));
            mx1 = fmaxf(mx1, fmaxf(s[n][2], s[n][3]));
        }
        mx0 = fmaxf(mx0, __shfl_xor_sync(0xffffffffu, mx0, 1));
        mx0 = fmaxf(mx0, __shfl_xor_sync(0xffffffffu, mx0, 2));
        mx1 = fmaxf(mx1, __shfl_xor_sync(0xffffffffu, mx1, 1));
        mx1 = fmaxf(mx1, __shfl_xor_sync(0xffffffffu, mx1, 2));

        float m0n = fmaxf(m0, mx0), m1n = fmaxf(m1, mx1);
        float c0 = expfast(m0 - m0n), c1 = expfast(m1 - m1n);
        float s0 = 0.f, s1 = 0.f;
#pragma unroll
        for (int n = 0; n < 8; n++) {
            s[n][0] = expfast(s[n][0] - m0n); s0 += s[n][0];
            s[n][1] = expfast(s[n][1] - m0n); s0 += s[n][1];
            s[n][2] = expfast(s[n][2] - m1n); s1 += s[n][2];
            s[n][3] = expfast(s[n][3] - m1n); s1 += s[n][3];
        }
        s0 += __shfl_xor_sync(0xffffffffu, s0, 1);
        s0 += __shfl_xor_sync(0xffffffffu, s0, 2);
        s1 += __shfl_xor_sync(0xffffffffu, s1, 1);
        s1 += __shfl_xor_sync(0xffffffffu, s1, 2);
        l0 = l0 * c0 + s0;
        l1 = l1 * c1 + s1;
        m0 = m0n; m1 = m1n;
#pragma unroll
        for (int nd = 0; nd < 8; nd++) {
            o[nd][0] *= c0; o[nd][1] *= c0;
            o[nd][2] *= c1; o[nd][3] *= c1;
        }

#pragma unroll
        for (int ksj = 0; ksj < 4; ksj++) {
            uint32_t pah[4], pal[4];
            pah[0] = bpack(s[2*ksj][0],   s[2*ksj][1]);
            pah[1] = bpack(s[2*ksj][2],   s[2*ksj][3]);
            pah[2] = bpack(s[2*ksj+1][0], s[2*ksj+1][1]);
            pah[3] = bpack(s[2*ksj+1][2], s[2*ksj+1][3]);
            pal[0] = bpack_lo(s[2*ksj][0],   s[2*ksj][1],   pah[0]);
            pal[1] = bpack_lo(s[2*ksj][2],   s[2*ksj][3],   pah[1]);
            pal[2] = bpack_lo(s[2*ksj+1][0], s[2*ksj+1][1], pah[2]);
            pal[3] = bpack_lo(s[2*ksj+1][2], s[2*ksj+1][3], pah[3]);

#pragma unroll
            for (int dbp = 0; dbp < 4; dbp++) {
                uint32_t vd = stg + (9216 + ksj * 1152 + v_base + dbp * 16) * 2;
                uint32_t h0, h1, h2, h3, lo0, lo1, lo2, lo3;
                LDSM_X4_T(h0, h1, h2, h3, vd);
                LDSM_X4_T(lo0, lo1, lo2, lo3, vd + 4608 * 2);
                mma_bf16(o[2*dbp],   pah, lo0, lo1);
                mma_bf16(o[2*dbp],   pal, h0, h1);
                mma_bf16(o[2*dbp],   pah, h0, h1);
                mma_bf16(o[2*dbp+1], pah, lo2, lo3);
                mma_bf16(o[2*dbp+1], pal, h2, h3);
                mma_bf16(o[2*dbp+1], pah, h2, h3);
            }
        }
        __syncthreads();
    }
#undef AISSUE

    float inv0 = 1.f / l0, inv1 = 1.f / l1;
    size_t row0 = (size_t)(b * TT + q0 + w * 16 + gid);
    size_t row1 = row0 + 8;
#pragma unroll
    for (int nd = 0; nd < 8; nd++) {
        int c = h * DH + nd * 8 + 2 * t4;
        float a0 = o[nd][0] * inv0, a1 = o[nd][1] * inv0;
        uint32_t hh = bpack(a0, a1);
        *(uint32_t*)(AttH + row0 * CC + c) = hh;
        *(uint32_t*)(AttL + row0 * CC + c) = bpack_lo(a0, a1, hh);
        float b0 = o[nd][2] * inv1, b1 = o[nd][3] * inv1;
        uint32_t hh2 = bpack(b0, b1);
        *(uint32_t*)(AttH + row1 * CC + c) = hh2;
        *(uint32_t*)(AttL + row1 * CC + c) = bpack_lo(b0, b1, hh2);
    }
}

// ---------------- launch ----------------------------------------------------
extern "C" void kernel_launch(void* const* d_in, const int* in_sizes, int n_in,
                              void* d_out, int out_size)
{
    const float* x    = (const float*)d_in[0];
    const float* Wqkv = (const float*)d_in[1];
    const float* bqkv = (const float*)d_in[2];
    const float* Wout = (const float*)d_in[3];
    const float* bout = (const float*)d_in[4];
    float* out = (float*)d_out;

    bf *p_xh, *p_xl, *p_wqh, *p_wql, *p_woh, *p_wol;
    bf *p_qh, *p_ql, *p_kh, *p_kl, *p_vh, *p_vl, *p_atth, *p_attl;
    float2* p_rope;
    cudaGetSymbolAddress((void**)&p_xh,   g_xh);
    cudaGetSymbolAddress((void**)&p_xl,   g_xl);
    cudaGetSymbolAddress((void**)&p_wqh,  g_wqh);
    cudaGetSymbolAddress((void**)&p_wql,  g_wql);
    cudaGetSymbolAddress((void**)&p_woh,  g_woh);
    cudaGetSymbolAddress((void**)&p_wol,  g_wol);
    cudaGetSymbolAddress((void**)&p_qh,   g_qh);
    cudaGetSymbolAddress((void**)&p_ql,   g_ql);
    cudaGetSymbolAddress((void**)&p_kh,   g_kh);
    cudaGetSymbolAddress((void**)&p_kl,   g_kl);
    cudaGetSymbolAddress((void**)&p_vh,   g_vh);
    cudaGetSymbolAddress((void**)&p_vl,   g_vl);
    cudaGetSymbolAddress((void**)&p_atth, g_atth);
    cudaGetSymbolAddress((void**)&p_attl, g_attl);
    cudaGetSymbolAddress((void**)&p_rope, g_rope);

    cudaFuncSetAttribute(gemm_hl<0>,
                         cudaFuncAttributeMaxDynamicSharedMemorySize, GEMM_SMEM);
    cudaFuncSetAttribute(gemm_hl<1>,
                         cudaFuncAttributeMaxDynamicSharedMemorySize, GEMM_SMEM);
    cudaFuncSetAttribute(attn_hl,
                         cudaFuncAttributeMaxDynamicSharedMemorySize, ASMEM);

    // 0) prep: weight transpose+split, x split, rope table
    transpose_split<<<dim3(3 * CC / 32, CC / 32), 256>>>(Wqkv, p_wqh, p_wql, CC, 3 * CC);
    transpose_split<<<dim3(CC / 32, CC / 32), 256>>>(Wout, p_woh, p_wol, CC, CC);
    splitf<<<(BT * CC / 4) / 256, 256>>>(x, p_xh, p_xl, BT * CC / 4);
    rope_table<<<(TT * 32) / 256, 256>>>(p_rope);

    // 1) QKV projection with fused bias+RoPE+split epilogue
    gemm_hl<1><<<dim3(3 * CC / 128, BT / 128), 256, GEMM_SMEM>>>(
        p_xh, p_xl, p_wqh, p_wql, bqkv, nullptr, p_rope,
        p_qh, p_ql, p_kh, p_kl, p_vh, p_vl, BT, 3 * CC, CC);

    // 2) attention
    attn_hl<<<dim3(TT / 128, BB * HH), 256, ASMEM>>>(
        p_qh, p_ql, p_kh, p_kl, p_vh, p_vl, p_atth, p_attl);

    // 3) output projection
    gemm_hl<0><<<dim3(CC / 128, BT / 128), 256, GEMM_SMEM>>>(
        p_atth, p_attl, p_woh, p_wol, bout, out, nullptr,
        nullptr, nullptr, nullptr, nullptr, nullptr, nullptr, BT, CC, CC);
}

// round 7
// speedup vs baseline: 3.6383x; 1.3799x over previous
#include <cuda_runtime.h>
#include <cuda_fp16.h>
#include <cstdint>
#include <math.h>

#define BB 4
#define TT 2048
#define CC 1024
#define HH 16
#define DH 64
#define BT (BB*TT)

typedef __half hf;

// ---------------- scratch (static device globals) ---------------------------
__device__ hf g_xh[(size_t)BT * CC],  g_xl[(size_t)BT * CC];
__device__ hf g_wq[(size_t)3 * CC * CC];          // W_qkv^T single fp16
__device__ hf g_wo[(size_t)CC * CC];              // W_out^T single fp16
__device__ hf g_qh[(size_t)BB*HH*TT*DH], g_ql[(size_t)BB*HH*TT*DH];
__device__ hf g_k1[(size_t)BB*HH*TT*DH];          // K single
__device__ hf g_v1[(size_t)BB*HH*TT*DH];          // V single
__device__ hf g_atth[(size_t)BT * CC], g_attl[(size_t)BT * CC];
__device__ float2 g_rope[(size_t)TT * 32];

// ================= helpers ===================================================
__device__ __forceinline__ uint32_t smem_u32(const void* p) {
    uint32_t a;
    asm("{ .reg .u64 t; cvta.to.shared.u64 t, %1; cvt.u32.u64 %0, t; }"
        : "=r"(a) : "l"(p));
    return a;
}
__device__ __forceinline__ uint32_t hpack(float a, float b) {
    __half2 t = __floats2half2_rn(a, b);
    return *reinterpret_cast<uint32_t*>(&t);
}
__device__ __forceinline__ uint32_t hpack_lo(float a, float b, uint32_t hp) {
    __half2 h = *reinterpret_cast<__half2*>(&hp);
    return hpack(a - __half2float(h.x), b - __half2float(h.y));
}
__device__ __forceinline__ void cvt4(float4 v, uint2& h, uint2& l) {
    h.x = hpack(v.x, v.y);
    h.y = hpack(v.z, v.w);
    l.x = hpack_lo(v.x, v.y, h.x);
    l.y = hpack_lo(v.z, v.w, h.y);
}
__device__ __forceinline__ void mma_f16(float* d, const uint32_t* a,
                                        uint32_t b0, uint32_t b1) {
    asm volatile(
        "mma.sync.aligned.m16n8k16.row.col.f32.f16.f16.f32 "
        "{%0,%1,%2,%3}, {%4,%5,%6,%7}, {%8,%9}, {%0,%1,%2,%3};"
        : "+f"(d[0]), "+f"(d[1]), "+f"(d[2]), "+f"(d[3])
        : "r"(a[0]), "r"(a[1]), "r"(a[2]), "r"(a[3]), "r"(b0), "r"(b1));
}
#define LDSM_X4(r0,r1,r2,r3,addr)                                             \
    asm volatile("ldmatrix.sync.aligned.m8n8.x4.shared.b16 {%0,%1,%2,%3}, [%4];" \
                 : "=r"(r0),"=r"(r1),"=r"(r2),"=r"(r3) : "r"(addr))
#define LDSM_X4_T(r0,r1,r2,r3,addr)                                           \
    asm volatile("ldmatrix.sync.aligned.m8n8.x4.trans.shared.b16 {%0,%1,%2,%3}, [%4];" \
                 : "=r"(r0),"=r"(r1),"=r"(r2),"=r"(r3) : "r"(addr))
#define CP16(dst, src)                                                        \
    asm volatile("cp.async.cg.shared.global [%0], [%1], 16;"                  \
                 :: "r"(dst), "l"(__cvta_generic_to_global((const void*)(src))))
#define CP_COMMIT() asm volatile("cp.async.commit_group;")
#define CP_WAIT(n)  asm volatile("cp.async.wait_group %0;" :: "n"(n))

// fast exp on FMA pipe (x <= 0)
__device__ __forceinline__ float expfast(float x) {
    float y = fmaxf(x * 1.4426950408889634f, -126.0f);
    int   ni = __float2int_rn(y);
    float f  = y - (float)ni;
    float p = 0.0013333558146428443f;
    p = fmaf(p, f, 0.009618129107628477f);
    p = fmaf(p, f, 0.05550410866482158f);
    p = fmaf(p, f, 0.2402265069591007f);
    p = fmaf(p, f, 0.6931471805599453f);
    p = fmaf(p, f, 1.0f);
    return p * __int_as_float((ni + 127) << 23);
}

// ================= prep kernels ==============================================
// W[K,N] -> single fp16 of W^T [N,K]
__global__ __launch_bounds__(256) void transpose_h(
    const float* __restrict__ W, hf* __restrict__ H, int K, int N)
{
    __shared__ float t[32][33];
    int n0 = blockIdx.x * 32, k0 = blockIdx.y * 32;
    int lx = threadIdx.x & 31, ly = threadIdx.x >> 5;
#pragma unroll
    for (int i = 0; i < 32; i += 8)
        t[ly + i][lx] = W[(size_t)(k0 + ly + i) * N + n0 + lx];
    __syncthreads();
#pragma unroll
    for (int i = 0; i < 32; i += 8)
        H[(size_t)(n0 + ly + i) * K + k0 + lx] = __float2half_rn(t[lx][ly + i]);
}

__global__ __launch_bounds__(256) void splitf(
    const float* __restrict__ A, hf* __restrict__ H, hf* __restrict__ L, int n4)
{
    int i = blockIdx.x * blockDim.x + threadIdx.x;
    if (i >= n4) return;
    float4 v = ((const float4*)A)[i];
    uint2 h, l;
    cvt4(v, h, l);
    ((uint2*)H)[i] = h;
    ((uint2*)L)[i] = l;
}

__global__ __launch_bounds__(256) void rope_table(float2* __restrict__ T)
{
    int i = blockIdx.x * 256 + threadIdx.x;
    int t = i >> 5, j = i & 31;
    float invf = exp2f(-(float)j * 0.41524101186f);
    float sn, cs;
    sincosf((float)t * invf, &sn, &cs);
    T[i] = make_float2(cs, sn);
}

// ================= fp16 2-term GEMM (3-stage cp.async + ldmatrix) ============
// C = (Ah+Al)[M,K] @ Bf[N,K]^T + bias   (error ~ A*(B - Bf) ~ 2^-12)
// CTA 128x128, BK=32, 8 warps (32m x 64n), 3-stage pipeline.
// stage (halves): Ah[128x40] @0, Al @5120, Bf @10240
#define GEMM_STG 15360
#define GEMM_SMEM (3 * GEMM_STG * 2)

template <int FR>
__global__ __launch_bounds__(256, 1) void gemm_hl(
    const hf* __restrict__ Ah, const hf* __restrict__ Al,
    const hf* __restrict__ Bf,
    const float* __restrict__ bias, float* __restrict__ C,
    const float2* __restrict__ ropeT,
    hf* __restrict__ Qh, hf* __restrict__ Ql,
    hf* __restrict__ K1, hf* __restrict__ V1,
    int M, int N, int K)
{
    extern __shared__ hf dsm[];
    const uint32_t smb = smem_u32(dsm);
    const int tid  = threadIdx.x;
    const int lane = tid & 31, gid = lane >> 2, t4 = lane & 3;
    const int wid  = tid >> 5;
    const int wm   = wid & 3, wn = wid >> 2;
    const int tile_n = blockIdx.x * 128, tile_m = blockIdx.y * 128;

    const hf* srcb[3];
    srcb[0] = Ah + (size_t)tile_m * K;
    srcb[1] = Al + (size_t)tile_m * K;
    srcb[2] = Bf + (size_t)tile_n * K;

    float acc[2][8][4];
#pragma unroll
    for (int ma = 0; ma < 2; ma++)
#pragma unroll
        for (int na = 0; na < 8; na++)
#pragma unroll
            for (int c = 0; c < 4; c++) acc[ma][na][c] = 0.f;

    const int kiters = K / 32;

    const int a_base = (lane & 15) * 40 + (lane >> 4) * 8 + wm * 32 * 40;
    const int b_base = ((lane & 7) + ((lane >> 4) & 1) * 8) * 40 +
                       ((lane >> 3) & 1) * 8 + wn * 64 * 40 + 10240;

#define GISSUE(IT, ST)                                                        \
    do {                                                                      \
        _Pragma("unroll")                                                     \
        for (int i = 0; i < 6; i++) {                                         \
            int idx = i * 256 + tid;                                          \
            int tile = i >> 1;                                                \
            int r = (idx >> 2) & 127, ch = idx & 3;                           \
            const hf* src = srcb[tile] + (size_t)r * K + (IT) * 32 + ch * 8;  \
            uint32_t dst = smb + ((ST) * GEMM_STG + tile * 5120 +             \
                                  r * 40 + ch * 8) * 2;                       \
            CP16(dst, src);                                                   \
        }                                                                     \
        CP_COMMIT();                                                          \
    } while (0)

    GISSUE(0, 0);
    GISSUE(1, 1);

    for (int it = 0; it < kiters; it++) {
        if (it + 1 < kiters) { CP_WAIT(1); } else { CP_WAIT(0); }
        __syncthreads();
        if (it + 2 < kiters) {
            const int st2 = (it + 2) % 3;
            GISSUE(it + 2, st2);
        }

        const uint32_t stg = smb + ((it % 3) * GEMM_STG) * 2;

#pragma unroll
        for (int ks = 0; ks < 2; ks++) {
            uint32_t ah[2][4], al[2][4];
#pragma unroll
            for (int ma = 0; ma < 2; ma++) {
                uint32_t ad = stg + (a_base + ma * 640 + ks * 16) * 2;
                LDSM_X4(ah[ma][0], ah[ma][1], ah[ma][2], ah[ma][3], ad);
                LDSM_X4(al[ma][0], al[ma][1], al[ma][2], al[ma][3],
                        ad + 5120 * 2);
            }
            uint32_t bh[4][4];
#pragma unroll
            for (int nb = 0; nb < 4; nb++) {
                uint32_t bd = stg + (b_base + nb * 640 + ks * 16) * 2;
                LDSM_X4(bh[nb][0], bh[nb][1], bh[nb][2], bh[nb][3], bd);
            }
#pragma unroll
            for (int nb = 0; nb < 4; nb++)
#pragma unroll
                for (int ma = 0; ma < 2; ma++) {
                    mma_f16(acc[ma][2*nb],   ah[ma], bh[nb][0], bh[nb][1]);
                    mma_f16(acc[ma][2*nb],   al[ma], bh[nb][0], bh[nb][1]);
                    mma_f16(acc[ma][2*nb+1], ah[ma], bh[nb][2], bh[nb][3]);
                    mma_f16(acc[ma][2*nb+1], al[ma], bh[nb][2], bh[nb][3]);
                }
        }
    }
#undef GISSUE

    if (FR == 0) {
        // ---- standard epilogue: bias + fp32 store ----
#pragma unroll
        for (int ma = 0; ma < 2; ma++) {
            const int r0 = tile_m + wm * 32 + ma * 16 + gid;
#pragma unroll
            for (int na = 0; na < 8; na++) {
                const int c0 = tile_n + wn * 64 + na * 8 + t4 * 2;
                float2 bv = *(const float2*)(bias + c0);
                *(float2*)(C + (size_t)r0 * N + c0) =
                    make_float2(acc[ma][na][0] + bv.x, acc[ma][na][1] + bv.y);
                *(float2*)(C + (size_t)(r0 + 8) * N + c0) =
                    make_float2(acc[ma][na][2] + bv.x, acc[ma][na][3] + bv.y);
            }
        }
    } else {
        // ---- fused epilogue: bias + RoPE + store Q split / K,V single ------
        const int win = tile_n + wn * 64;
        const int typ = win >> 10;                // 0=q 1=k 2=v
        const int hd  = (win & 1023) >> 6;
        const float scale = (typ == 0) ? 0.125f : 1.f;

#pragma unroll
        for (int ma = 0; ma < 2; ma++) {
#pragma unroll
            for (int rh = 0; rh < 2; rh++) {
                const int row = tile_m + wm * 32 + ma * 16 + gid + rh * 8;
                const int bb = row >> 11, tt = row & 2047;
                const size_t obase = ((size_t)(bb * HH + hd) * TT + tt) * DH;
#pragma unroll
                for (int na = 0; na < 4; na++) {
                    const int j0 = na * 8 + t4 * 2;
                    const int c0 = win + j0;
                    float a0 = acc[ma][na][2*rh+0]   + bias[c0];
                    float a1 = acc[ma][na][2*rh+1]   + bias[c0 + 1];
                    float b0 = acc[ma][na+4][2*rh+0] + bias[c0 + 32];
                    float b1 = acc[ma][na+4][2*rh+1] + bias[c0 + 33];
                    float2 cs0 = make_float2(1.f, 0.f), cs1 = cs0;
                    if (typ < 2) {
                        cs0 = ropeT[tt * 32 + j0];
                        cs1 = ropeT[tt * 32 + j0 + 1];
                    }
                    float o0 = (a0 * cs0.x - b0 * cs0.y) * scale;
                    float p0 = (b0 * cs0.x + a0 * cs0.y) * scale;
                    float o1 = (a1 * cs1.x - b1 * cs1.y) * scale;
                    float p1 = (b1 * cs1.x + a1 * cs1.y) * scale;
                    if (typ == 0) {
                        uint32_t h0 = hpack(o0, o1);
                        *(uint32_t*)(Qh + obase + j0) = h0;
                        *(uint32_t*)(Ql + obase + j0) = hpack_lo(o0, o1, h0);
                        uint32_t h1 = hpack(p0, p1);
                        *(uint32_t*)(Qh + obase + j0 + 32) = h1;
                        *(uint32_t*)(Ql + obase + j0 + 32) = hpack_lo(p0, p1, h1);
                    } else {
                        hf* O1 = (typ == 1) ? K1 : V1;
                        *(uint32_t*)(O1 + obase + j0)      = hpack(o0, o1);
                        *(uint32_t*)(O1 + obase + j0 + 32) = hpack(p0, p1);
                    }
                }
            }
        }
    }
}

// ================= FA2 attention: fp16 2-term, cp.async + ldmatrix ===========
// CTA: 128 q rows, 256 threads (8 warps x 16q). 64-key tiles, double-buffered.
// smem (halves): Qh[128x72]@0, Ql@9216; stages@18432+st*9216:
//   per stage Kh@0, Vh@4608 (each 64x72)
#define ASTG  9216
#define ASMEM ((18432 + 2 * 9216) * 2)

__global__ __launch_bounds__(256, 1) void attn_hl(
    const hf* __restrict__ Qh, const hf* __restrict__ Ql,
    const hf* __restrict__ K1, const hf* __restrict__ V1,
    hf* __restrict__ AttH, hf* __restrict__ AttL)
{
    extern __shared__ hf dsm[];
    const uint32_t smb = smem_u32(dsm);
    const int tid = threadIdx.x;
    const int lane = tid & 31, gid = lane >> 2, t4 = lane & 3;
    const int w = tid >> 5;
    const int bh = blockIdx.y;
    const int q0 = blockIdx.x * 128;
    const int b = bh >> 4, h = bh & 15;

    const size_t hoff = (size_t)bh * TT * DH;
    const hf* kvsrc[2];
    kvsrc[0] = K1 + hoff;
    kvsrc[1] = V1 + hoff;

#define AISSUE(KB, ST)                                                       \
    do {                                                                     \
        _Pragma("unroll")                                                    \
        for (int i = 0; i < 4; i++) {                                        \
            int idx = i * 256 + tid;                                         \
            int tile = i >> 1;                                               \
            int r = (idx >> 3) & 63, ch = idx & 7;                           \
            const hf* src = kvsrc[tile] + (size_t)((KB) + r) * DH + ch * 8;  \
            uint32_t dst = smb + (18432 + (ST) * ASTG + tile * 4608 +        \
                                  r * 72 + ch * 8) * 2;                      \
            CP16(dst, src);                                                  \
        }                                                                    \
        CP_COMMIT();                                                         \
    } while (0)

    // ---- stage Q ----
    {
        const hf* qsrc[2];
        qsrc[0] = Qh + hoff + (size_t)q0 * DH;
        qsrc[1] = Ql + hoff + (size_t)q0 * DH;
#pragma unroll
        for (int i = 0; i < 8; i++) {
            int idx = i * 256 + tid;
            int arr = i >> 2;
            int r = (idx >> 3) & 127, ch = idx & 7;
            const hf* src = qsrc[arr] + (size_t)r * DH + ch * 8;
            uint32_t dst = smb + (arr * 9216 + r * 72 + ch * 8) * 2;
            CP16(dst, src);
        }
        CP_COMMIT();
    }
    AISSUE(0, 0);
    CP_WAIT(1);
    __syncthreads();

    uint32_t qhf[4][4], qlf[4][4];
    {
        const uint32_t qb = smb + ((w * 16 + (lane & 15)) * 72 + (lane >> 4) * 8) * 2;
#pragma unroll
        for (int ks = 0; ks < 4; ks++) {
            LDSM_X4(qhf[ks][0], qhf[ks][1], qhf[ks][2], qhf[ks][3], qb + ks * 32);
            LDSM_X4(qlf[ks][0], qlf[ks][1], qlf[ks][2], qlf[ks][3],
                    qb + ks * 32 + 9216 * 2);
        }
    }

    float m0 = -1e30f, m1 = -1e30f, l0 = 0.f, l1 = 0.f;
    float o[8][4];
#pragma unroll
    for (int nd = 0; nd < 8; nd++)
#pragma unroll
        for (int c = 0; c < 4; c++) o[nd][c] = 0.f;

    const int k_base = ((lane & 7) + ((lane >> 4) & 1) * 8) * 72 +
                       ((lane >> 3) & 1) * 8;
    const int v_base = ((lane & 7) + ((lane >> 3) & 1) * 8) * 72 +
                       ((lane >> 4) & 1) * 8;

    const int ntiles = TT / 64;
    for (int it = 0; it < ntiles; it++) {
        const int st = it & 1;
        if (it + 1 < ntiles) {
            AISSUE((it + 1) * 64, st ^ 1);
            CP_WAIT(1);
        } else {
            CP_WAIT(0);
        }
        __syncthreads();

        const uint32_t stg = smb + (18432 + st * ASTG) * 2;

        float s[8][4];
#pragma unroll
        for (int n = 0; n < 8; n++)
#pragma unroll
            for (int c = 0; c < 4; c++) s[n][c] = 0.f;

#pragma unroll
        for (int ks = 0; ks < 4; ks++) {
#pragma unroll
            for (int nb = 0; nb < 4; nb++) {
                uint32_t kd = stg + (nb * 1152 + k_base + ks * 16) * 2;
                uint32_t h0, h1, h2, h3;
                LDSM_X4(h0, h1, h2, h3, kd);
                mma_f16(s[2*nb],   qhf[ks], h0, h1);
                mma_f16(s[2*nb],   qlf[ks], h0, h1);
                mma_f16(s[2*nb+1], qhf[ks], h2, h3);
                mma_f16(s[2*nb+1], qlf[ks], h2, h3);
            }
        }

        float mx0 = -1e30f, mx1 = -1e30f;
#pragma unroll
        for (int n = 0; n < 8; n++) {
            mx0 = fmaxf(mx0, fmaxf(s[n][0], s[n][1]));
            mx1 = fmaxf(mx1, fmaxf(s[n][2], s[n][3]));
        }
        mx0 = fmaxf(mx0, __shfl_xor_sync(0xffffffffu, mx0, 1));
        mx0 = fmaxf(mx0, __shfl_xor_sync(0xffffffffu, mx0, 2));
        mx1 = fmaxf(mx1, __shfl_xor_sync(0xffffffffu, mx1, 1));
        mx1 = fmaxf(mx1, __shfl_xor_sync(0xffffffffu, mx1, 2));

        float m0n = fmaxf(m0, mx0), m1n = fmaxf(m1, mx1);
        float c0 = expfast(m0 - m0n), c1 = expfast(m1 - m1n);
        float s0 = 0.f, s1 = 0.f;
#pragma unroll
        for (int n = 0; n < 8; n++) {
            s[n][0] = expfast(s[n][0] - m0n); s0 += s[n][0];
            s[n][1] = expfast(s[n][1] - m0n); s0 += s[n][1];
            s[n][2] = expfast(s[n][2] - m1n); s1 += s[n][2];
            s[n][3] = expfast(s[n][3] - m1n); s1 += s[n][3];
        }
        s0 += __shfl_xor_sync(0xffffffffu, s0, 1);
        s0 += __shfl_xor_sync(0xffffffffu, s0, 2);
        s1 += __shfl_xor_sync(0xffffffffu, s1, 1);
        s1 += __shfl_xor_sync(0xffffffffu, s1, 2);
        l0 = l0 * c0 + s0;
        l1 = l1 * c1 + s1;
        m0 = m0n; m1 = m1n;
#pragma unroll
        for (int nd = 0; nd < 8; nd++) {
            o[nd][0] *= c0; o[nd][1] *= c0;
            o[nd][2] *= c1; o[nd][3] *= c1;
        }

#pragma unroll
        for (int ksj = 0; ksj < 4; ksj++) {
            uint32_t pah[4], pal[4];
            pah[0] = hpack(s[2*ksj][0],   s[2*ksj][1]);
            pah[1] = hpack(s[2*ksj][2],   s[2*ksj][3]);
            pah[2] = hpack(s[2*ksj+1][0], s[2*ksj+1][1]);
            pah[3] = hpack(s[2*ksj+1][2], s[2*ksj+1][3]);
            pal[0] = hpack_lo(s[2*ksj][0],   s[2*ksj][1],   pah[0]);
            pal[1] = hpack_lo(s[2*ksj][2],   s[2*ksj][3],   pah[1]);
            pal[2] = hpack_lo(s[2*ksj+1][0], s[2*ksj+1][1], pah[2]);
            pal[3] = hpack_lo(s[2*ksj+1][2], s[2*ksj+1][3], pah[3]);

#pragma unroll
            for (int dbp = 0; dbp < 4; dbp++) {
                uint32_t vd = stg + (4608 + ksj * 1152 + v_base + dbp * 16) * 2;
                uint32_t h0, h1, h2, h3;
                LDSM_X4_T(h0, h1, h2, h3, vd);
                mma_f16(o[2*dbp],   pah, h0, h1);
                mma_f16(o[2*dbp],   pal, h0, h1);
                mma_f16(o[2*dbp+1], pah, h2, h3);
                mma_f16(o[2*dbp+1], pal, h2, h3);
            }
        }
        __syncthreads();
    }
#undef AISSUE

    float inv0 = 1.f / l0, inv1 = 1.f / l1;
    size_t row0 = (size_t)(b * TT + q0 + w * 16 + gid);
    size_t row1 = row0 + 8;
#pragma unroll
    for (int nd = 0; nd < 8; nd++) {
        int c = h * DH + nd * 8 + 2 * t4;
        float a0 = o[nd][0] * inv0, a1 = o[nd][1] * inv0;
        uint32_t hh = hpack(a0, a1);
        *(uint32_t*)(AttH + row0 * CC + c) = hh;
        *(uint32_t*)(AttL + row0 * CC + c) = hpack_lo(a0, a1, hh);
        float b0 = o[nd][2] * inv1, b1 = o[nd][3] * inv1;
        uint32_t hh2 = hpack(b0, b1);
        *(uint32_t*)(AttH + row1 * CC + c) = hh2;
        *(uint32_t*)(AttL + row1 * CC + c) = hpack_lo(b0, b1, hh2);
    }
}

// ---------------- launch ----------------------------------------------------
extern "C" void kernel_launch(void* const* d_in, const int* in_sizes, int n_in,
                              void* d_out, int out_size)
{
    const float* x    = (const float*)d_in[0];
    const float* Wqkv = (const float*)d_in[1];
    const float* bqkv = (const float*)d_in[2];
    const float* Wout = (const float*)d_in[3];
    const float* bout = (const float*)d_in[4];
    float* out = (float*)d_out;

    hf *p_xh, *p_xl, *p_wq, *p_wo;
    hf *p_qh, *p_ql, *p_k1, *p_v1, *p_atth, *p_attl;
    float2* p_rope;
    cudaGetSymbolAddress((void**)&p_xh,   g_xh);
    cudaGetSymbolAddress((void**)&p_xl,   g_xl);
    cudaGetSymbolAddress((void**)&p_wq,   g_wq);
    cudaGetSymbolAddress((void**)&p_wo,   g_wo);
    cudaGetSymbolAddress((void**)&p_qh,   g_qh);
    cudaGetSymbolAddress((void**)&p_ql,   g_ql);
    cudaGetSymbolAddress((void**)&p_k1,   g_k1);
    cudaGetSymbolAddress((void**)&p_v1,   g_v1);
    cudaGetSymbolAddress((void**)&p_atth, g_atth);
    cudaGetSymbolAddress((void**)&p_attl, g_attl);
    cudaGetSymbolAddress((void**)&p_rope, g_rope);

    cudaFuncSetAttribute(gemm_hl<0>,
                         cudaFuncAttributeMaxDynamicSharedMemorySize, GEMM_SMEM);
    cudaFuncSetAttribute(gemm_hl<1>,
                         cudaFuncAttributeMaxDynamicSharedMemorySize, GEMM_SMEM);
    cudaFuncSetAttribute(attn_hl,
                         cudaFuncAttributeMaxDynamicSharedMemorySize, ASMEM);

    // 0) prep
    transpose_h<<<dim3(3 * CC / 32, CC / 32), 256>>>(Wqkv, p_wq, CC, 3 * CC);
    transpose_h<<<dim3(CC / 32, CC / 32), 256>>>(Wout, p_wo, CC, CC);
    splitf<<<(BT * CC / 4) / 256, 256>>>(x, p_xh, p_xl, BT * CC / 4);
    rope_table<<<(TT * 32) / 256, 256>>>(p_rope);

    // 1) QKV projection with fused bias+RoPE+split epilogue
    gemm_hl<1><<<dim3(3 * CC / 128, BT / 128), 256, GEMM_SMEM>>>(
        p_xh, p_xl, p_wq, bqkv, nullptr, p_rope,
        p_qh, p_ql, p_k1, p_v1, BT, 3 * CC, CC);

    // 2) attention
    attn_hl<<<dim3(TT / 128, BB * HH), 256, ASMEM>>>(
        p_qh, p_ql, p_k1, p_v1, p_atth, p_attl);

    // 3) output projection
    gemm_hl<0><<<dim3(CC / 128, BT / 128), 256, GEMM_SMEM>>>(
        p_atth, p_attl, p_wo, bout, out, nullptr,
        nullptr, nullptr, nullptr, nullptr, BT, CC, CC);
}

// round 8
// speedup vs baseline: 5.0865x; 1.3980x over previous
#include <cuda_runtime.h>
#include <cuda_fp16.h>
#include <cstdint>
#include <math.h>

#define BB 4
#define TT 2048
#define CC 1024
#define HH 16
#define DH 64
#define BT (BB*TT)

typedef __half hf;

// ---------------- scratch (static device globals) ---------------------------
__device__ hf g_x1[(size_t)BT * CC];              // x fp16
__device__ hf g_wq[(size_t)3 * CC * CC];          // W_qkv^T fp16
__device__ hf g_wo[(size_t)CC * CC];              // W_out^T fp16
__device__ hf g_q1[(size_t)BB*HH*TT*DH];
__device__ hf g_k1[(size_t)BB*HH*TT*DH];
__device__ hf g_v1[(size_t)BB*HH*TT*DH];
__device__ hf g_att1[(size_t)BT * CC];
__device__ float2 g_rope[(size_t)TT * 32];

// ================= helpers ===================================================
__device__ __forceinline__ uint32_t smem_u32(const void* p) {
    uint32_t a;
    asm("{ .reg .u64 t; cvta.to.shared.u64 t, %1; cvt.u32.u64 %0, t; }"
        : "=r"(a) : "l"(p));
    return a;
}
__device__ __forceinline__ uint32_t hpack(float a, float b) {
    __half2 t = __floats2half2_rn(a, b);
    return *reinterpret_cast<uint32_t*>(&t);
}
__device__ __forceinline__ void mma_f16(float* d, const uint32_t* a,
                                        uint32_t b0, uint32_t b1) {
    asm volatile(
        "mma.sync.aligned.m16n8k16.row.col.f32.f16.f16.f32 "
        "{%0,%1,%2,%3}, {%4,%5,%6,%7}, {%8,%9}, {%0,%1,%2,%3};"
        : "+f"(d[0]), "+f"(d[1]), "+f"(d[2]), "+f"(d[3])
        : "r"(a[0]), "r"(a[1]), "r"(a[2]), "r"(a[3]), "r"(b0), "r"(b1));
}
#define LDSM_X4(r0,r1,r2,r3,addr)                                             \
    asm volatile("ldmatrix.sync.aligned.m8n8.x4.shared.b16 {%0,%1,%2,%3}, [%4];" \
                 : "=r"(r0),"=r"(r1),"=r"(r2),"=r"(r3) : "r"(addr))
#define LDSM_X4_T(r0,r1,r2,r3,addr)                                           \
    asm volatile("ldmatrix.sync.aligned.m8n8.x4.trans.shared.b16 {%0,%1,%2,%3}, [%4];" \
                 : "=r"(r0),"=r"(r1),"=r"(r2),"=r"(r3) : "r"(addr))
#define CP16(dst, src)                                                        \
    asm volatile("cp.async.cg.shared.global [%0], [%1], 16;"                  \
                 :: "r"(dst), "l"(__cvta_generic_to_global((const void*)(src))))
#define CP_COMMIT() asm volatile("cp.async.commit_group;")
#define CP_WAIT(n)  asm volatile("cp.async.wait_group %0;" :: "n"(n))

// fast exp on FMA pipe (x <= 0)
__device__ __forceinline__ float expfast(float x) {
    float y = fmaxf(x * 1.4426950408889634f, -126.0f);
    int   ni = __float2int_rn(y);
    float f  = y - (float)ni;
    float p = 0.0013333558146428443f;
    p = fmaf(p, f, 0.009618129107628477f);
    p = fmaf(p, f, 0.05550410866482158f);
    p = fmaf(p, f, 0.2402265069591007f);
    p = fmaf(p, f, 0.6931471805599453f);
    p = fmaf(p, f, 1.0f);
    return p * __int_as_float((ni + 127) << 23);
}

// ================= prep kernels ==============================================
__global__ __launch_bounds__(256) void transpose_h(
    const float* __restrict__ W, hf* __restrict__ H, int K, int N)
{
    __shared__ float t[32][33];
    int n0 = blockIdx.x * 32, k0 = blockIdx.y * 32;
    int lx = threadIdx.x & 31, ly = threadIdx.x >> 5;
#pragma unroll
    for (int i = 0; i < 32; i += 8)
        t[ly + i][lx] = W[(size_t)(k0 + ly + i) * N + n0 + lx];
    __syncthreads();
#pragma unroll
    for (int i = 0; i < 32; i += 8)
        H[(size_t)(n0 + ly + i) * K + k0 + lx] = __float2half_rn(t[lx][ly + i]);
}

__global__ __launch_bounds__(256) void cvtx(
    const float* __restrict__ A, hf* __restrict__ H, int n4)
{
    int i = blockIdx.x * blockDim.x + threadIdx.x;
    if (i >= n4) return;
    float4 v = ((const float4*)A)[i];
    uint2 h;
    h.x = hpack(v.x, v.y);
    h.y = hpack(v.z, v.w);
    ((uint2*)H)[i] = h;
}

__global__ __launch_bounds__(256) void rope_table(float2* __restrict__ T)
{
    int i = blockIdx.x * 256 + threadIdx.x;
    int t = i >> 5, j = i & 31;
    float invf = exp2f(-(float)j * 0.41524101186f);
    float sn, cs;
    sincosf((float)t * invf, &sn, &cs);
    T[i] = make_float2(cs, sn);
}

// ================= fp16 GEMM (3-stage cp.async + ldmatrix) ===================
// C = A[M,K] @ B[N,K]^T + bias, fp32 accum
// CTA 128x128, BK=32, 8 warps (32m x 64n), 3-stage pipeline.
// stage (halves): A[128x40] @0, B[128x40] @5120
#define GEMM_STG 10240
#define GEMM_SMEM (3 * GEMM_STG * 2)

template <int FR>
__global__ __launch_bounds__(256, 1) void gemm_f16(
    const hf* __restrict__ A, const hf* __restrict__ B,
    const float* __restrict__ bias, float* __restrict__ C,
    const float2* __restrict__ ropeT,
    hf* __restrict__ Q1, hf* __restrict__ K1, hf* __restrict__ V1,
    int M, int N, int K)
{
    extern __shared__ hf dsm[];
    const uint32_t smb = smem_u32(dsm);
    const int tid  = threadIdx.x;
    const int lane = tid & 31, gid = lane >> 2, t4 = lane & 3;
    const int wid  = tid >> 5;
    const int wm   = wid & 3, wn = wid >> 2;
    const int tile_n = blockIdx.x * 128, tile_m = blockIdx.y * 128;

    const hf* srcb[2];
    srcb[0] = A + (size_t)tile_m * K;
    srcb[1] = B + (size_t)tile_n * K;

    float acc[2][8][4];
#pragma unroll
    for (int ma = 0; ma < 2; ma++)
#pragma unroll
        for (int na = 0; na < 8; na++)
#pragma unroll
            for (int c = 0; c < 4; c++) acc[ma][na][c] = 0.f;

    const int kiters = K / 32;

    const int a_base = (lane & 15) * 40 + (lane >> 4) * 8 + wm * 32 * 40;
    const int b_base = ((lane & 7) + ((lane >> 4) & 1) * 8) * 40 +
                       ((lane >> 3) & 1) * 8 + wn * 64 * 40 + 5120;

#define GISSUE(IT, ST)                                                        \
    do {                                                                      \
        _Pragma("unroll")                                                     \
        for (int i = 0; i < 4; i++) {                                         \
            int idx = i * 256 + tid;                                          \
            int tile = i >> 1;                                                \
            int r = (idx >> 2) & 127, ch = idx & 3;                           \
            const hf* src = srcb[tile] + (size_t)r * K + (IT) * 32 + ch * 8;  \
            uint32_t dst = smb + ((ST) * GEMM_STG + tile * 5120 +             \
                                  r * 40 + ch * 8) * 2;                       \
            CP16(dst, src);                                                   \
        }                                                                     \
        CP_COMMIT();                                                          \
    } while (0)

    GISSUE(0, 0);
    GISSUE(1, 1);

    for (int it = 0; it < kiters; it++) {
        if (it + 1 < kiters) { CP_WAIT(1); } else { CP_WAIT(0); }
        __syncthreads();
        if (it + 2 < kiters) {
            const int st2 = (it + 2) % 3;
            GISSUE(it + 2, st2);
        }

        const uint32_t stg = smb + ((it % 3) * GEMM_STG) * 2;

#pragma unroll
        for (int ks = 0; ks < 2; ks++) {
            uint32_t ah[2][4];
#pragma unroll
            for (int ma = 0; ma < 2; ma++) {
                uint32_t ad = stg + (a_base + ma * 640 + ks * 16) * 2;
                LDSM_X4(ah[ma][0], ah[ma][1], ah[ma][2], ah[ma][3], ad);
            }
            uint32_t bh[4][4];
#pragma unroll
            for (int nb = 0; nb < 4; nb++) {
                uint32_t bd = stg + (b_base + nb * 640 + ks * 16) * 2;
                LDSM_X4(bh[nb][0], bh[nb][1], bh[nb][2], bh[nb][3], bd);
            }
#pragma unroll
            for (int nb = 0; nb < 4; nb++)
#pragma unroll
                for (int ma = 0; ma < 2; ma++) {
                    mma_f16(acc[ma][2*nb],   ah[ma], bh[nb][0], bh[nb][1]);
                    mma_f16(acc[ma][2*nb+1], ah[ma], bh[nb][2], bh[nb][3]);
                }
        }
    }
#undef GISSUE

    if (FR == 0) {
        // ---- standard epilogue: bias + fp32 store ----
#pragma unroll
        for (int ma = 0; ma < 2; ma++) {
            const int r0 = tile_m + wm * 32 + ma * 16 + gid;
#pragma unroll
            for (int na = 0; na < 8; na++) {
                const int c0 = tile_n + wn * 64 + na * 8 + t4 * 2;
                float2 bv = *(const float2*)(bias + c0);
                *(float2*)(C + (size_t)r0 * N + c0) =
                    make_float2(acc[ma][na][0] + bv.x, acc[ma][na][1] + bv.y);
                *(float2*)(C + (size_t)(r0 + 8) * N + c0) =
                    make_float2(acc[ma][na][2] + bv.x, acc[ma][na][3] + bv.y);
            }
        }
    } else {
        // ---- fused epilogue: bias + RoPE + fp16 store -> [B,H,T,Dh] ----
        const int win = tile_n + wn * 64;
        const int typ = win >> 10;                // 0=q 1=k 2=v
        const int hd  = (win & 1023) >> 6;
        hf* O1 = (typ == 0) ? Q1 : (typ == 1) ? K1 : V1;
        const float scale = (typ == 0) ? 0.125f : 1.f;

#pragma unroll
        for (int ma = 0; ma < 2; ma++) {
#pragma unroll
            for (int rh = 0; rh < 2; rh++) {
                const int row = tile_m + wm * 32 + ma * 16 + gid + rh * 8;
                const int bb = row >> 11, tt = row & 2047;
                const size_t obase = ((size_t)(bb * HH + hd) * TT + tt) * DH;
#pragma unroll
                for (int na = 0; na < 4; na++) {
                    const int j0 = na * 8 + t4 * 2;
                    const int c0 = win + j0;
                    float a0 = acc[ma][na][2*rh+0]   + bias[c0];
                    float a1 = acc[ma][na][2*rh+1]   + bias[c0 + 1];
                    float b0 = acc[ma][na+4][2*rh+0] + bias[c0 + 32];
                    float b1 = acc[ma][na+4][2*rh+1] + bias[c0 + 33];
                    float2 cs0 = make_float2(1.f, 0.f), cs1 = cs0;
                    if (typ < 2) {
                        cs0 = ropeT[tt * 32 + j0];
                        cs1 = ropeT[tt * 32 + j0 + 1];
                    }
                    float o0 = (a0 * cs0.x - b0 * cs0.y) * scale;
                    float p0 = (b0 * cs0.x + a0 * cs0.y) * scale;
                    float o1 = (a1 * cs1.x - b1 * cs1.y) * scale;
                    float p1 = (b1 * cs1.x + a1 * cs1.y) * scale;
                    *(uint32_t*)(O1 + obase + j0)      = hpack(o0, o1);
                    *(uint32_t*)(O1 + obase + j0 + 32) = hpack(p0, p1);
                }
            }
        }
    }
}

// ================= FA2 attention: fp16, cp.async + ldmatrix ==================
// CTA: 128 q rows, 256 threads (8 warps x 16q). 64-key tiles, double-buffered.
// smem (halves): Q[128x72]@0; stages@9216+st*9216: K@0, V@4608 (each 64x72)
#define ASTG  9216
#define ASMEM ((9216 + 2 * 9216) * 2)

__global__ __launch_bounds__(256, 1) void attn_f16(
    const hf* __restrict__ Q1, const hf* __restrict__ K1,
    const hf* __restrict__ V1, hf* __restrict__ Att1)
{
    extern __shared__ hf dsm[];
    const uint32_t smb = smem_u32(dsm);
    const int tid = threadIdx.x;
    const int lane = tid & 31, gid = lane >> 2, t4 = lane & 3;
    const int w = tid >> 5;
    const int bh = blockIdx.y;
    const int q0 = blockIdx.x * 128;
    const int b = bh >> 4, h = bh & 15;

    const size_t hoff = (size_t)bh * TT * DH;
    const hf* kvsrc[2];
    kvsrc[0] = K1 + hoff;
    kvsrc[1] = V1 + hoff;

#define AISSUE(KB, ST)                                                       \
    do {                                                                     \
        _Pragma("unroll")                                                    \
        for (int i = 0; i < 4; i++) {                                        \
            int idx = i * 256 + tid;                                         \
            int tile = i >> 1;                                               \
            int r = (idx >> 3) & 63, ch = idx & 7;                           \
            const hf* src = kvsrc[tile] + (size_t)((KB) + r) * DH + ch * 8;  \
            uint32_t dst = smb + (9216 + (ST) * ASTG + tile * 4608 +         \
                                  r * 72 + ch * 8) * 2;                      \
            CP16(dst, src);                                                  \
        }                                                                    \
        CP_COMMIT();                                                         \
    } while (0)

    // ---- stage Q ----
    {
        const hf* qsrc = Q1 + hoff + (size_t)q0 * DH;
#pragma unroll
        for (int i = 0; i < 4; i++) {
            int idx = i * 256 + tid;
            int r = (idx >> 3) & 127, ch = idx & 7;
            uint32_t dst = smb + (r * 72 + ch * 8) * 2;
            CP16(dst, qsrc + (size_t)r * DH + ch * 8);
        }
        CP_COMMIT();
    }
    AISSUE(0, 0);
    CP_WAIT(1);
    __syncthreads();

    uint32_t qhf[4][4];
    {
        const uint32_t qb = smb + ((w * 16 + (lane & 15)) * 72 + (lane >> 4) * 8) * 2;
#pragma unroll
        for (int ks = 0; ks < 4; ks++)
            LDSM_X4(qhf[ks][0], qhf[ks][1], qhf[ks][2], qhf[ks][3], qb + ks * 32);
    }

    float m0 = -1e30f, m1 = -1e30f, l0 = 0.f, l1 = 0.f;
    float o[8][4];
#pragma unroll
    for (int nd = 0; nd < 8; nd++)
#pragma unroll
        for (int c = 0; c < 4; c++) o[nd][c] = 0.f;

    const int k_base = ((lane & 7) + ((lane >> 4) & 1) * 8) * 72 +
                       ((lane >> 3) & 1) * 8;
    const int v_base = ((lane & 7) + ((lane >> 3) & 1) * 8) * 72 +
                       ((lane >> 4) & 1) * 8;

    const int ntiles = TT / 64;
    for (int it = 0; it < ntiles; it++) {
        const int st = it & 1;
        if (it + 1 < ntiles) {
            AISSUE((it + 1) * 64, st ^ 1);
            CP_WAIT(1);
        } else {
            CP_WAIT(0);
        }
        __syncthreads();

        const uint32_t stg = smb + (9216 + st * ASTG) * 2;

        float s[8][4];
#pragma unroll
        for (int n = 0; n < 8; n++)
#pragma unroll
            for (int c = 0; c < 4; c++) s[n][c] = 0.f;

#pragma unroll
        for (int ks = 0; ks < 4; ks++) {
#pragma unroll
            for (int nb = 0; nb < 4; nb++) {
                uint32_t kd = stg + (nb * 1152 + k_base + ks * 16) * 2;
                uint32_t h0, h1, h2, h3;
                LDSM_X4(h0, h1, h2, h3, kd);
                mma_f16(s[2*nb],   qhf[ks], h0, h1);
                mma_f16(s[2*nb+1], qhf[ks], h2, h3);
            }
        }

        float mx0 = -1e30f, mx1 = -1e30f;
#pragma unroll
        for (int n = 0; n < 8; n++) {
            mx0 = fmaxf(mx0, fmaxf(s[n][0], s[n][1]));
            mx1 = fmaxf(mx1, fmaxf(s[n][2], s[n][3]));
        }
        mx0 = fmaxf(mx0, __shfl_xor_sync(0xffffffffu, mx0, 1));
        mx0 = fmaxf(mx0, __shfl_xor_sync(0xffffffffu, mx0, 2));
        mx1 = fmaxf(mx1, __shfl_xor_sync(0xffffffffu, mx1, 1));
        mx1 = fmaxf(mx1, __shfl_xor_sync(0xffffffffu, mx1, 2));

        float m0n = fmaxf(m0, mx0), m1n = fmaxf(m1, mx1);
        float c0 = expfast(m0 - m0n), c1 = expfast(m1 - m1n);
        float s0 = 0.f, s1 = 0.f;
#pragma unroll
        for (int n = 0; n < 8; n++) {
            s[n][0] = expfast(s[n][0] - m0n); s0 += s[n][0];
            s[n][1] = expfast(s[n][1] - m0n); s0 += s[n][1];
            s[n][2] = expfast(s[n][2] - m1n); s1 += s[n][2];
            s[n][3] = expfast(s[n][3] - m1n); s1 += s[n][3];
        }
        s0 += __shfl_xor_sync(0xffffffffu, s0, 1);
        s0 += __shfl_xor_sync(0xffffffffu, s0, 2);
        s1 += __shfl_xor_sync(0xffffffffu, s1, 1);
        s1 += __shfl_xor_sync(0xffffffffu, s1, 2);
        l0 = l0 * c0 + s0;
        l1 = l1 * c1 + s1;
        m0 = m0n; m1 = m1n;
#pragma unroll
        for (int nd = 0; nd < 8; nd++) {
            o[nd][0] *= c0; o[nd][1] *= c0;
            o[nd][2] *= c1; o[nd][3] *= c1;
        }

#pragma unroll
        for (int ksj = 0; ksj < 4; ksj++) {
            uint32_t pah[4];
            pah[0] = hpack(s[2*ksj][0],   s[2*ksj][1]);
            pah[1] = hpack(s[2*ksj][2],   s[2*ksj][3]);
            pah[2] = hpack(s[2*ksj+1][0], s[2*ksj+1][1]);
            pah[3] = hpack(s[2*ksj+1][2], s[2*ksj+1][3]);

#pragma unroll
            for (int dbp = 0; dbp < 4; dbp++) {
                uint32_t vd = stg + (4608 + ksj * 1152 + v_base + dbp * 16) * 2;
                uint32_t h0, h1, h2, h3;
                LDSM_X4_T(h0, h1, h2, h3, vd);
                mma_f16(o[2*dbp],   pah, h0, h1);
                mma_f16(o[2*dbp+1], pah, h2, h3);
            }
        }
        __syncthreads();
    }
#undef AISSUE

    float inv0 = 1.f / l0, inv1 = 1.f / l1;
    size_t row0 = (size_t)(b * TT + q0 + w * 16 + gid);
    size_t row1 = row0 + 8;
#pragma unroll
    for (int nd = 0; nd < 8; nd++) {
        int c = h * DH + nd * 8 + 2 * t4;
        *(uint32_t*)(Att1 + row0 * CC + c) =
            hpack(o[nd][0] * inv0, o[nd][1] * inv0);
        *(uint32_t*)(Att1 + row1 * CC + c) =
            hpack(o[nd][2] * inv1, o[nd][3] * inv1);
    }
}

// ---------------- launch ----------------------------------------------------
extern "C" void kernel_launch(void* const* d_in, const int* in_sizes, int n_in,
                              void* d_out, int out_size)
{
    const float* x    = (const float*)d_in[0];
    const float* Wqkv = (const float*)d_in[1];
    const float* bqkv = (const float*)d_in[2];
    const float* Wout = (const float*)d_in[3];
    const float* bout = (const float*)d_in[4];
    float* out = (float*)d_out;

    hf *p_x1, *p_wq, *p_wo, *p_q1, *p_k1, *p_v1, *p_att1;
    float2* p_rope;
    cudaGetSymbolAddress((void**)&p_x1,   g_x1);
    cudaGetSymbolAddress((void**)&p_wq,   g_wq);
    cudaGetSymbolAddress((void**)&p_wo,   g_wo);
    cudaGetSymbolAddress((void**)&p_q1,   g_q1);
    cudaGetSymbolAddress((void**)&p_k1,   g_k1);
    cudaGetSymbolAddress((void**)&p_v1,   g_v1);
    cudaGetSymbolAddress((void**)&p_att1, g_att1);
    cudaGetSymbolAddress((void**)&p_rope, g_rope);

    cudaFuncSetAttribute(gemm_f16<0>,
                         cudaFuncAttributeMaxDynamicSharedMemorySize, GEMM_SMEM);
    cudaFuncSetAttribute(gemm_f16<1>,
                         cudaFuncAttributeMaxDynamicSharedMemorySize, GEMM_SMEM);
    cudaFuncSetAttribute(attn_f16,
                         cudaFuncAttributeMaxDynamicSharedMemorySize, ASMEM);

    // 0) prep
    transpose_h<<<dim3(3 * CC / 32, CC / 32), 256>>>(Wqkv, p_wq, CC, 3 * CC);
    transpose_h<<<dim3(CC / 32, CC / 32), 256>>>(Wout, p_wo, CC, CC);
    cvtx<<<(BT * CC / 4) / 256, 256>>>(x, p_x1, BT * CC / 4);
    rope_table<<<(TT * 32) / 256, 256>>>(p_rope);

    // 1) QKV projection with fused bias+RoPE epilogue
    gemm_f16<1><<<dim3(3 * CC / 128, BT / 128), 256, GEMM_SMEM>>>(
        p_x1, p_wq, bqkv, nullptr, p_rope,
        p_q1, p_k1, p_v1, BT, 3 * CC, CC);

    // 2) attention
    attn_f16<<<dim3(TT / 128, BB * HH), 256, ASMEM>>>(
        p_q1, p_k1, p_v1, p_att1);

    // 3) output projection
    gemm_f16<0><<<dim3(CC / 128, BT / 128), 256, GEMM_SMEM>>>(
        p_att1, p_wo, bout, out, nullptr,
        nullptr, nullptr, nullptr, BT, CC, CC);
}